// round 11
// baseline (speedup 1.0000x reference)
#include <cuda_runtime.h>
#include <cuda_bf16.h>
#include <cstdint>

// Problem constants
#define BQ   8
#define CQi  256
#define CKV  512
#define NN   4096
#define DQK  32

typedef unsigned long long ull;
typedef unsigned int uint32;

// ---------------- scratch (static device globals; no allocations) ----------
__device__ float          g_kv[BQ * CKV * NN];  // resized key_value [b][c][n]
__device__ float          g_q [BQ * NN * DQK];  // Q^T [b][n][d] (tf32-rounded)
__device__ float          g_k [BQ * DQK * NN];  // K   [b][d][n] (tf32-rounded)
__device__ __nv_bfloat16  g_v [BQ * CQi * NN];  // V   [b][c][n] (bf16)

// ---------------- helpers ---------------------------------------------------
__device__ __forceinline__ float tf32r(float x) {
    uint32 u;
    asm("cvt.rna.tf32.f32 %0, %1;" : "=r"(u) : "f"(x));
    return __uint_as_float(u);
}
__device__ __forceinline__ void mma_tf32(
    float& c0, float& c1, float& c2, float& c3,
    uint32 a0, uint32 a1, uint32 a2, uint32 a3,
    uint32 b0, uint32 b1)
{
    asm volatile(
        "mma.sync.aligned.m16n8k8.row.col.f32.tf32.tf32.f32 "
        "{%0,%1,%2,%3}, {%4,%5,%6,%7}, {%8,%9}, {%0,%1,%2,%3};"
        : "+f"(c0), "+f"(c1), "+f"(c2), "+f"(c3)
        : "r"(a0), "r"(a1), "r"(a2), "r"(a3), "r"(b0), "r"(b1));
}
__device__ __forceinline__ void mma_bf16(
    float& c0, float& c1, float& c2, float& c3,
    uint32 a0, uint32 a1, uint32 a2, uint32 a3,
    uint32 b0, uint32 b1)
{
    asm volatile(
        "mma.sync.aligned.m16n8k16.row.col.f32.bf16.bf16.f32 "
        "{%0,%1,%2,%3}, {%4,%5,%6,%7}, {%8,%9}, {%0,%1,%2,%3};"
        : "+f"(c0), "+f"(c1), "+f"(c2), "+f"(c3)
        : "r"(a0), "r"(a1), "r"(a2), "r"(a3), "r"(b0), "r"(b1));
}
__device__ __forceinline__ void cp16p(void* sdst, const void* gsrc) {
    uint32 s = (uint32)__cvta_generic_to_shared(sdst);
    asm volatile("cp.async.cg.shared.global [%0], [%1], 16;" :: "r"(s), "l"(gsrc));
}
__device__ __forceinline__ void cp_commit() {
    asm volatile("cp.async.commit_group;" ::: "memory");
}
__device__ __forceinline__ void cp_wait0() {
    asm volatile("cp.async.wait_group 0;" ::: "memory");
}

// ---------------- bilinear 2x upsample (half-pixel, clamped) ---------------
__global__ void resize_kernel(const float* __restrict__ src) {
    int idx = blockIdx.x * 256 + threadIdx.x;
    if (idx >= BQ * CKV * NN) return;
    int x  = idx & 63;
    int y  = (idx >> 6) & 63;
    int cb = idx >> 12;
    float fx = 0.5f * (float)x - 0.25f;
    float fy = 0.5f * (float)y - 0.25f;
    float fx0 = floorf(fx), fy0 = floorf(fy);
    float wx = fx - fx0, wy = fy - fy0;
    int x0 = max((int)fx0, 0), x1 = min((int)fx0 + 1, 31);
    int y0 = max((int)fy0, 0), y1 = min((int)fy0 + 1, 31);
    const float* s = src + (size_t)cb * 1024;
    float v00 = s[y0 * 32 + x0], v01 = s[y0 * 32 + x1];
    float v10 = s[y1 * 32 + x0], v11 = s[y1 * 32 + x1];
    float top = v00 + wx * (v01 - v00);
    float bot = v10 + wx * (v11 - v10);
    g_kv[idx] = top + wy * (bot - top);
}

// ---------------- tf32-mma 1x1 conv GEMM -----------------------------------
// OUTM: 1 = tf32 transposed [n][DQK] (Q), 2 = tf32 [d][n] f32 (K),
//       3 = bf16 [d][n] (V)
template <int CIN, int DT, int NT, int WM, int WN, int OUTM>
__global__ __launch_bounds__(256, 2) void proj_mma(
    const float* __restrict__ in, const float* __restrict__ W,
    const float* __restrict__ bias, void* __restrict__ outp, int dout_total)
{
    constexpr int BK  = 32;
    constexpr int NTP = NT + 4;
    constexpr int WSP = 36;
    constexpr int KCH = CIN / BK;
    constexpr int MT  = WM / 16;
    constexpr int NTl = WN / 8;
    constexpr int WARPS_N = NT / WN;

    extern __shared__ float smx[];
    float* ins = smx;
    float* Ws  = smx + 2 * BK * NTP;

    int tid  = threadIdx.x;
    int warp = tid >> 5, lane = tid & 31;
    int lr = lane >> 2, lc = lane & 3;
    int nwarp = warp % WARPS_N, mwarp = warp / WARPS_N;
    int mb = mwarp * WM, nb = nwarp * WN;

    int b  = blockIdx.y;
    int n0 = blockIdx.x * NT;
    int d0 = blockIdx.z * DT;

    const float* inb = in + (size_t)b * CIN * NN + n0;

    float acc[MT][NTl][4];
#pragma unroll
    for (int mt = 0; mt < MT; mt++)
#pragma unroll
        for (int nt = 0; nt < NTl; nt++)
#pragma unroll
            for (int i = 0; i < 4; i++) acc[mt][nt][i] = 0.f;

    auto prefetch = [&](int kc, int pb) {
        float* insB = ins + pb * BK * NTP;
        float* WsB  = Ws  + pb * DT * WSP;
        constexpr int INIT = BK * NT / 4 / 256;
#pragma unroll
        for (int it = 0; it < INIT; it++) {
            int idx = tid + it * 256;
            int c = idx / (NT / 4), j4 = (idx % (NT / 4)) * 4;
            cp16p(insB + c * NTP + j4, inb + (size_t)(kc * BK + c) * NN + j4);
        }
        constexpr int WIT = DT * 8 / 256;
#pragma unroll
        for (int it = 0; it < (WIT > 0 ? WIT : 1); it++) {
            int idx = tid + it * 256;
            if (idx < DT * 8) {
                int d = idx >> 3, cj = (idx & 7) * 4;
                cp16p(WsB + d * WSP + cj, W + (size_t)(d0 + d) * CIN + kc * BK + cj);
            }
        }
    };

    prefetch(0, 0);
    cp_commit();
    cp_wait0();
    __syncthreads();

    for (int kc = 0; kc < KCH; kc++) {
        int buf = kc & 1;
        if (kc + 1 < KCH) { prefetch(kc + 1, buf ^ 1); cp_commit(); }
        const float* insB = ins + buf * BK * NTP;
        const float* WsB  = Ws  + buf * DT * WSP;
#pragma unroll
        for (int kk = 0; kk < 4; kk++) {
            uint32 a[MT][4];
#pragma unroll
            for (int mt = 0; mt < MT; mt++) {
                const float* ar = WsB + (mb + mt * 16 + lr) * WSP + kk * 8 + lc;
                a[mt][0] = __float_as_uint(ar[0]);
                a[mt][1] = __float_as_uint(ar[8 * WSP]);
                a[mt][2] = __float_as_uint(ar[4]);
                a[mt][3] = __float_as_uint(ar[8 * WSP + 4]);
            }
            const float* br = insB + (kk * 8 + lc) * NTP + nb + lr;
#pragma unroll
            for (int nt = 0; nt < NTl; nt++) {
                uint32 b0 = __float_as_uint(br[nt * 8]);
                uint32 b1 = __float_as_uint(br[4 * NTP + nt * 8]);
#pragma unroll
                for (int mt = 0; mt < MT; mt++)
                    mma_tf32(acc[mt][nt][0], acc[mt][nt][1],
                             acc[mt][nt][2], acc[mt][nt][3],
                             a[mt][0], a[mt][1], a[mt][2], a[mt][3], b0, b1);
            }
        }
        cp_wait0();
        __syncthreads();
    }

#pragma unroll
    for (int mt = 0; mt < MT; mt++) {
        int dA = d0 + mb + mt * 16 + lr;
        float bA = bias[dA], bB = bias[dA + 8];
        if (OUTM == 1) {
            float* op = (float*)outp;
#pragma unroll
            for (int nt = 0; nt < NTl; nt++) {
                int nc = n0 + nb + nt * 8 + 2 * lc;
                float* o = op + ((size_t)b * NN + nc) * DQK;
                o[dA]           = tf32r(acc[mt][nt][0] + bA);
                o[DQK + dA]     = tf32r(acc[mt][nt][1] + bA);
                o[dA + 8]       = tf32r(acc[mt][nt][2] + bB);
                o[DQK + dA + 8] = tf32r(acc[mt][nt][3] + bB);
            }
        } else if (OUTM == 2) {
            float* oA = (float*)outp + ((size_t)b * dout_total + dA) * NN + n0 + nb;
            float* oB = oA + (size_t)8 * NN;
#pragma unroll
            for (int nt = 0; nt < NTl; nt++) {
                int col = nt * 8 + 2 * lc;
                *(float2*)&oA[col] = make_float2(tf32r(acc[mt][nt][0] + bA),
                                                tf32r(acc[mt][nt][1] + bA));
                *(float2*)&oB[col] = make_float2(tf32r(acc[mt][nt][2] + bB),
                                                tf32r(acc[mt][nt][3] + bB));
            }
        } else {
            __nv_bfloat16* oA = (__nv_bfloat16*)outp
                + ((size_t)b * dout_total + dA) * NN + n0 + nb;
            __nv_bfloat16* oB = oA + (size_t)8 * NN;
#pragma unroll
            for (int nt = 0; nt < NTl; nt++) {
                int col = nt * 8 + 2 * lc;
                *(__nv_bfloat162*)&oA[col] =
                    __floats2bfloat162_rn(acc[mt][nt][0] + bA, acc[mt][nt][1] + bA);
                *(__nv_bfloat162*)&oB[col] =
                    __floats2bfloat162_rn(acc[mt][nt][2] + bB, acc[mt][nt][3] + bB);
            }
        }
    }
}

// ---------------- flash attention: tf32 S + bf16 PV, occ-2 -----------------
// BM=64 rows/CTA, BN=32 KV cols/iter, 256 threads (8 warps), 2 CTAs/SM.
// Iteration t: S(t) mma -> PV(t-1) mma -> exp(t) -> store P(t); one barrier.
// P double-buffered, V triple-buffered, K double-buffered.
// Fragment addressing identical to the validated R9/R10 kernels.
#define BM 64
#define BN 32
#define QSTR 36     // floats
#define KSTR 40     // floats
#define VSTRB 40    // bf16 elements (32 data + 8 pad; 80B rows)
#define PSTRB 40    // bf16 elements

#define KSLOT 5120      // 32*40*4 bytes
#define VSLOT 20480     // 256*40*2 bytes
#define PSLOT 5120      // 64*40*2 bytes

#define OFF_QS 0                              // 64*36*4  = 9216
#define OFF_K  9216                           // 2*KSLOT  = 10240
#define OFF_V  19456                          // 3*VSLOT  = 61440
#define OFF_P  80896                          // 2*PSLOT  = 10240
#define OFF_L  91136                          // 2*64*4   = 512
#define ATT_SMEM 91648

__global__ __launch_bounds__(256, 2) void attn_kernel(
    const float* __restrict__ qT, const float* __restrict__ k,
    const __nv_bfloat16* __restrict__ v, const float* __restrict__ query,
    const float* __restrict__ gamma, float* __restrict__ outp)
{
    extern __shared__ char smem[];
    float*         qs = (float*)(smem + OFF_QS);
    float*         ks = (float*)(smem + OFF_K);
    __nv_bfloat16* vs = (__nv_bfloat16*)(smem + OFF_V);
    __nv_bfloat16* ps = (__nv_bfloat16*)(smem + OFF_P);
    float*         lp = (float*)(smem + OFF_L);

    int tid  = threadIdx.x;
    int warp = tid >> 5;           // 0..7
    int lane = tid & 31;
    int lr = lane >> 2, lc = lane & 3;
    int b  = blockIdx.y;
    int i0 = blockIdx.x * BM;

    // S-phase mapping: 4 row-groups x 2 col-groups (16 rows x 16 cols/warp)
    int srow  = (warp & 3) * 16;
    int chalf = warp >> 2;
    int scol  = chalf * 16;
    // PV-phase mapping: 2 row-groups x 4 channel-groups (32 rows x 64 ch/warp)
    int pvrow = (warp & 1) * 32;
    int cb    = (warp >> 1) * 64;

    const float*         qTb = qT + ((size_t)b * NN + i0) * DQK;
    const float*         kb  = k  + (size_t)b * DQK * NN;
    const __nv_bfloat16* vb  = v  + (size_t)b * CQi * NN;

    auto prefetchKV = [&](int m0, int kslot, int vslot) {
        // K tile [32 d][32 j] f32: 256 chunks of 16B
        {
            int d = tid >> 3, ch = tid & 7;
            cp16p((char*)ks + kslot * KSLOT + d * (KSTR * 4) + ch * 16,
                  kb + (size_t)d * NN + m0 + ch * 4);
        }
        // V tile [256 c][32 j] bf16: 1024 chunks of 16B
#pragma unroll
        for (int it = 0; it < 4; it++) {
            int idx = tid + it * 256;
            int c = idx >> 2, ch = idx & 3;
            cp16p((char*)vs + vslot * VSLOT + c * (VSTRB * 2) + ch * 16,
                  vb + (size_t)c * NN + m0 + ch * 8);
        }
    };

    // ---- prolog: load Q tile [64 rows][32 d] + K(0),V(0) ----
#pragma unroll
    for (int it = 0; it < 2; it++) {
        int idx = tid + it * 256;
        int i = idx >> 3, ch = idx & 7;
        cp16p((char*)qs + i * (QSTR * 4) + ch * 16, qTb + i * DQK + ch * 4);
    }
    prefetchKV(0, 0, 0);
    cp_commit();
    cp_wait0();
    __syncthreads();

    float lsum0 = 0.f, lsum1 = 0.f;
    float acc[2][8][4];
#pragma unroll
    for (int mt = 0; mt < 2; mt++)
#pragma unroll
        for (int nt = 0; nt < 8; nt++)
#pragma unroll
            for (int i = 0; i < 4; i++) acc[mt][nt][i] = 0.f;

    const int NIT = NN / BN;   // 128

    for (int t = 0; t <= NIT; t++) {
        if (t < NIT && t + 1 < NIT) {
            prefetchKV((t + 1) * BN, (t + 1) & 1, (t + 1) % 3);
            cp_commit();
        }

        // ---- S(t) = Q K^T (tf32): 16 rows x 16 cols per warp ----
        float sc[2][4];
        if (t < NIT) {
#pragma unroll
            for (int nt = 0; nt < 2; nt++)
#pragma unroll
                for (int i = 0; i < 4; i++) sc[nt][i] = 0.f;
            const float* ksB = (const float*)((char*)ks + (t & 1) * KSLOT);
#pragma unroll
            for (int kk = 0; kk < 4; kk++) {
                const float* ar = qs + (srow + lr) * QSTR + kk * 8 + lc;
                uint32 a0 = __float_as_uint(ar[0]);
                uint32 a1 = __float_as_uint(ar[8 * QSTR]);
                uint32 a2 = __float_as_uint(ar[4]);
                uint32 a3 = __float_as_uint(ar[8 * QSTR + 4]);
                const float* br = ksB + (kk * 8 + lc) * KSTR + scol + lr;
#pragma unroll
                for (int nt = 0; nt < 2; nt++) {
                    uint32 b0 = __float_as_uint(br[nt * 8]);
                    uint32 b1 = __float_as_uint(br[4 * KSTR + nt * 8]);
                    mma_tf32(sc[nt][0], sc[nt][1], sc[nt][2], sc[nt][3],
                             a0, a1, a2, a3, b0, b1);
                }
            }
        }

        // ---- PV(t-1): acc += P V (bf16), 32 rows x 64 ch per warp ----
        if (t > 0) {
            int tp = t - 1;
            const __nv_bfloat16* psB =
                (const __nv_bfloat16*)((char*)ps + (tp & 1) * PSLOT);
            const __nv_bfloat16* vsB =
                (const __nv_bfloat16*)((char*)vs + (tp % 3) * VSLOT);
#pragma unroll
            for (int kk = 0; kk < 2; kk++) {
                uint32 a[2][4];
#pragma unroll
                for (int mt = 0; mt < 2; mt++) {
                    const __nv_bfloat16* ar =
                        psB + (pvrow + mt * 16 + lr) * PSTRB + kk * 16 + 2 * lc;
                    a[mt][0] = *(const uint32*)(ar);
                    a[mt][1] = *(const uint32*)(ar + 8 * PSTRB);
                    a[mt][2] = *(const uint32*)(ar + 8);
                    a[mt][3] = *(const uint32*)(ar + 8 * PSTRB + 8);
                }
#pragma unroll
                for (int nt = 0; nt < 8; nt++) {
                    const __nv_bfloat16* br =
                        vsB + (cb + nt * 8 + lr) * VSTRB + kk * 16 + 2 * lc;
                    uint32 b0 = *(const uint32*)(br);
                    uint32 b1 = *(const uint32*)(br + 8);
#pragma unroll
                    for (int mt = 0; mt < 2; mt++)
                        mma_bf16(acc[mt][nt][0], acc[mt][nt][1],
                                 acc[mt][nt][2], acc[mt][nt][3],
                                 a[mt][0], a[mt][1], a[mt][2], a[mt][3], b0, b1);
                }
            }
        }

        // ---- exp(t) (hidden under PV issue), store P(t) ----
        if (t < NIT) {
            __nv_bfloat16* psW = (__nv_bfloat16*)((char*)ps + (t & 1) * PSLOT);
#pragma unroll
            for (int nt = 0; nt < 2; nt++) {
                float p0 = __expf(sc[nt][0]);
                float p1 = __expf(sc[nt][1]);
                float p2 = __expf(sc[nt][2]);
                float p3 = __expf(sc[nt][3]);
                __nv_bfloat162 h0 = __floats2bfloat162_rn(p0, p1);
                __nv_bfloat162 h1 = __floats2bfloat162_rn(p2, p3);
                float2 r0f = __bfloat1622float2(h0);
                float2 r1f = __bfloat1622float2(h1);
                lsum0 += r0f.x + r0f.y;
                lsum1 += r1f.x + r1f.y;
                int col = scol + nt * 8 + 2 * lc;
                *(__nv_bfloat162*)&psW[(srow + lr) * PSTRB + col]     = h0;
                *(__nv_bfloat162*)&psW[(srow + lr + 8) * PSTRB + col] = h1;
            }
            cp_wait0();
            __syncthreads();   // single barrier: P(t) + K/V(t+1) visible
        }
    }

    // ---- row-sum reduction across the quad + col-halves ----
    lsum0 += __shfl_xor_sync(0xffffffffu, lsum0, 1);
    lsum0 += __shfl_xor_sync(0xffffffffu, lsum0, 2);
    lsum1 += __shfl_xor_sync(0xffffffffu, lsum1, 1);
    lsum1 += __shfl_xor_sync(0xffffffffu, lsum1, 2);
    if (lc == 0) {
        lp[chalf * BM + srow + lr]     = lsum0;
        lp[chalf * BM + srow + lr + 8] = lsum1;
    }
    __syncthreads();

    // ---- epilogue: out = gamma * acc / l + query ----
    float gm = gamma[0];
    const float* qry = query + (size_t)b * CQi * NN + i0;
    float*       ob  = outp  + (size_t)b * CQi * NN + i0;
#pragma unroll
    for (int mt = 0; mt < 2; mt++) {
        int r0 = pvrow + mt * 16 + lr;
        int r1 = r0 + 8;
        float f0 = gm / (lp[r0] + lp[BM + r0]);
        float f1 = gm / (lp[r1] + lp[BM + r1]);
#pragma unroll
        for (int nt = 0; nt < 8; nt++) {
            int c = cb + nt * 8 + 2 * lc;
            size_t o00 = (size_t)c * NN + r0;
            size_t o01 = (size_t)(c + 1) * NN + r0;
            size_t o10 = (size_t)c * NN + r1;
            size_t o11 = (size_t)(c + 1) * NN + r1;
            ob[o00] = f0 * acc[mt][nt][0] + qry[o00];
            ob[o01] = f0 * acc[mt][nt][1] + qry[o01];
            ob[o10] = f1 * acc[mt][nt][2] + qry[o10];
            ob[o11] = f1 * acc[mt][nt][3] + qry[o11];
        }
    }
}

// ---------------- host launcher -------------------------------------------
extern "C" void kernel_launch(void* const* d_in, const int* in_sizes, int n_in,
                              void* d_out, int out_size)
{
    const float* query     = (const float*)d_in[0];
    const float* key_value = (const float*)d_in[1];
    const float* Wq = (const float*)d_in[2];
    const float* bq = (const float*)d_in[3];
    const float* Wk = (const float*)d_in[4];
    const float* bk = (const float*)d_in[5];
    const float* Wv = (const float*)d_in[6];
    const float* bv = (const float*)d_in[7];
    const float* gamma = (const float*)d_in[8];
    float* out = (float*)d_out;

    void* p;
    cudaGetSymbolAddress(&p, g_kv); float*         kvb  = (float*)p;
    cudaGetSymbolAddress(&p, g_q);  float*         qb   = (float*)p;
    cudaGetSymbolAddress(&p, g_k);  float*         kb   = (float*)p;
    cudaGetSymbolAddress(&p, g_v);  __nv_bfloat16* vbuf = (__nv_bfloat16*)p;

    // 1) bilinear upsample
    resize_kernel<<<(BQ * CKV * NN + 255) / 256, 256>>>(key_value);

    // 2) projections: Q -> tf32 transposed, K -> tf32 [d][n], V -> bf16 [d][n]
    {
        size_t smQ = (2 * 32 * 260 + 2 * 32 * 36) * sizeof(float);
        size_t smV = (2 * 32 * 132 + 2 * 128 * 36) * sizeof(float);
        cudaFuncSetAttribute(proj_mma<256, 32, 256, 16, 64, 1>,
                             cudaFuncAttributeMaxDynamicSharedMemorySize, (int)smQ);
        cudaFuncSetAttribute(proj_mma<512, 32, 256, 16, 64, 2>,
                             cudaFuncAttributeMaxDynamicSharedMemorySize, (int)smQ);
        cudaFuncSetAttribute(proj_mma<512, 128, 128, 32, 64, 3>,
                             cudaFuncAttributeMaxDynamicSharedMemorySize, (int)smV);
        proj_mma<256, 32, 256, 16, 64, 1><<<dim3(16, 8, 1), 256, smQ>>>(query, Wq, bq, qb, 32);
        proj_mma<512, 32, 256, 16, 64, 2><<<dim3(16, 8, 1), 256, smQ>>>(kvb, Wk, bk, kb, 32);
        proj_mma<512, 128, 128, 32, 64, 3><<<dim3(32, 8, 2), 256, smV>>>(kvb, Wv, bv, vbuf, 256);
    }

    // 3) flash attention + residual (occ 2)
    cudaFuncSetAttribute(attn_kernel, cudaFuncAttributeMaxDynamicSharedMemorySize,
                         ATT_SMEM);
    attn_kernel<<<dim3(NN / BM, BQ), 256, ATT_SMEM>>>(qb, kb, vbuf, query,
                                                      gamma, out);
}

// round 12
// speedup vs baseline: 1.1745x; 1.1745x over previous
#include <cuda_runtime.h>
#include <cuda_bf16.h>
#include <cstdint>

// Problem constants
#define BQ   8
#define CQi  256
#define CKV  512
#define NN   4096
#define DQK  32

typedef unsigned long long ull;
typedef unsigned int uint32;

// ---------------- scratch (static device globals; no allocations) ----------
__device__ float          g_kv[BQ * CKV * NN];  // resized key_value [b][c][n]
__device__ float          g_q [BQ * NN * DQK];  // Q^T [b][n][d] (tf32-rounded)
__device__ float          g_k [BQ * DQK * NN];  // K   [b][d][n] (tf32-rounded)
__device__ __nv_bfloat16  g_v [BQ * CQi * NN];  // V   [b][c][n] (bf16)

// ---------------- helpers ---------------------------------------------------
__device__ __forceinline__ float tf32r(float x) {
    uint32 u;
    asm("cvt.rna.tf32.f32 %0, %1;" : "=r"(u) : "f"(x));
    return __uint_as_float(u);
}
__device__ __forceinline__ void mma_tf32(
    float& c0, float& c1, float& c2, float& c3,
    uint32 a0, uint32 a1, uint32 a2, uint32 a3,
    uint32 b0, uint32 b1)
{
    asm volatile(
        "mma.sync.aligned.m16n8k8.row.col.f32.tf32.tf32.f32 "
        "{%0,%1,%2,%3}, {%4,%5,%6,%7}, {%8,%9}, {%0,%1,%2,%3};"
        : "+f"(c0), "+f"(c1), "+f"(c2), "+f"(c3)
        : "r"(a0), "r"(a1), "r"(a2), "r"(a3), "r"(b0), "r"(b1));
}
__device__ __forceinline__ void mma_bf16(
    float& c0, float& c1, float& c2, float& c3,
    uint32 a0, uint32 a1, uint32 a2, uint32 a3,
    uint32 b0, uint32 b1)
{
    asm volatile(
        "mma.sync.aligned.m16n8k16.row.col.f32.bf16.bf16.f32 "
        "{%0,%1,%2,%3}, {%4,%5,%6,%7}, {%8,%9}, {%0,%1,%2,%3};"
        : "+f"(c0), "+f"(c1), "+f"(c2), "+f"(c3)
        : "r"(a0), "r"(a1), "r"(a2), "r"(a3), "r"(b0), "r"(b1));
}
__device__ __forceinline__ void cp16p(void* sdst, const void* gsrc) {
    uint32 s = (uint32)__cvta_generic_to_shared(sdst);
    asm volatile("cp.async.cg.shared.global [%0], [%1], 16;" :: "r"(s), "l"(gsrc));
}
__device__ __forceinline__ void cp_commit() {
    asm volatile("cp.async.commit_group;" ::: "memory");
}
__device__ __forceinline__ void cp_wait0() {
    asm volatile("cp.async.wait_group 0;" ::: "memory");
}

// ---------------- bilinear 2x upsample (half-pixel, clamped) ---------------
__global__ void resize_kernel(const float* __restrict__ src) {
    int idx = blockIdx.x * 256 + threadIdx.x;
    if (idx >= BQ * CKV * NN) return;
    int x  = idx & 63;
    int y  = (idx >> 6) & 63;
    int cb = idx >> 12;
    float fx = 0.5f * (float)x - 0.25f;
    float fy = 0.5f * (float)y - 0.25f;
    float fx0 = floorf(fx), fy0 = floorf(fy);
    float wx = fx - fx0, wy = fy - fy0;
    int x0 = max((int)fx0, 0), x1 = min((int)fx0 + 1, 31);
    int y0 = max((int)fy0, 0), y1 = min((int)fy0 + 1, 31);
    const float* s = src + (size_t)cb * 1024;
    float v00 = s[y0 * 32 + x0], v01 = s[y0 * 32 + x1];
    float v10 = s[y1 * 32 + x0], v11 = s[y1 * 32 + x1];
    float top = v00 + wx * (v01 - v00);
    float bot = v10 + wx * (v11 - v10);
    g_kv[idx] = top + wy * (bot - top);
}

// ---------------- tf32-mma 1x1 conv GEMM -----------------------------------
// OUTM: 1 = tf32 transposed [n][DQK] (Q), 2 = tf32 [d][n] f32 (K),
//       3 = bf16 [d][n] (V)
template <int CIN, int DT, int NT, int WM, int WN, int OUTM>
__global__ __launch_bounds__(256) void proj_mma(
    const float* __restrict__ in, const float* __restrict__ W,
    const float* __restrict__ bias, void* __restrict__ outp, int dout_total)
{
    constexpr int BK  = 32;
    constexpr int NTP = NT + 4;
    constexpr int WSP = 36;
    constexpr int KCH = CIN / BK;
    constexpr int MT  = WM / 16;
    constexpr int NTl = WN / 8;
    constexpr int WARPS_N = NT / WN;

    extern __shared__ float smx[];
    float* ins = smx;
    float* Ws  = smx + 2 * BK * NTP;

    int tid  = threadIdx.x;
    int warp = tid >> 5, lane = tid & 31;
    int lr = lane >> 2, lc = lane & 3;
    int nwarp = warp % WARPS_N, mwarp = warp / WARPS_N;
    int mb = mwarp * WM, nb = nwarp * WN;

    int b  = blockIdx.y;
    int n0 = blockIdx.x * NT;
    int d0 = blockIdx.z * DT;

    const float* inb = in + (size_t)b * CIN * NN + n0;

    float acc[MT][NTl][4];
#pragma unroll
    for (int mt = 0; mt < MT; mt++)
#pragma unroll
        for (int nt = 0; nt < NTl; nt++)
#pragma unroll
            for (int i = 0; i < 4; i++) acc[mt][nt][i] = 0.f;

    auto prefetch = [&](int kc, int pb) {
        float* insB = ins + pb * BK * NTP;
        float* WsB  = Ws  + pb * DT * WSP;
        constexpr int INIT = BK * NT / 4 / 256;
#pragma unroll
        for (int it = 0; it < INIT; it++) {
            int idx = tid + it * 256;
            int c = idx / (NT / 4), j4 = (idx % (NT / 4)) * 4;
            cp16p(insB + c * NTP + j4, inb + (size_t)(kc * BK + c) * NN + j4);
        }
        constexpr int WIT = DT * 8 / 256;
#pragma unroll
        for (int it = 0; it < (WIT > 0 ? WIT : 1); it++) {
            int idx = tid + it * 256;
            if (idx < DT * 8) {
                int d = idx >> 3, cj = (idx & 7) * 4;
                cp16p(WsB + d * WSP + cj, W + (size_t)(d0 + d) * CIN + kc * BK + cj);
            }
        }
    };

    prefetch(0, 0);
    cp_commit();
    cp_wait0();
    __syncthreads();

    for (int kc = 0; kc < KCH; kc++) {
        int buf = kc & 1;
        if (kc + 1 < KCH) { prefetch(kc + 1, buf ^ 1); cp_commit(); }
        const float* insB = ins + buf * BK * NTP;
        const float* WsB  = Ws  + buf * DT * WSP;
#pragma unroll
        for (int kk = 0; kk < 4; kk++) {
            uint32 a[MT][4];
#pragma unroll
            for (int mt = 0; mt < MT; mt++) {
                const float* ar = WsB + (mb + mt * 16 + lr) * WSP + kk * 8 + lc;
                a[mt][0] = __float_as_uint(ar[0]);
                a[mt][1] = __float_as_uint(ar[8 * WSP]);
                a[mt][2] = __float_as_uint(ar[4]);
                a[mt][3] = __float_as_uint(ar[8 * WSP + 4]);
            }
            const float* br = insB + (kk * 8 + lc) * NTP + nb + lr;
#pragma unroll
            for (int nt = 0; nt < NTl; nt++) {
                uint32 b0 = __float_as_uint(br[nt * 8]);
                uint32 b1 = __float_as_uint(br[4 * NTP + nt * 8]);
#pragma unroll
                for (int mt = 0; mt < MT; mt++)
                    mma_tf32(acc[mt][nt][0], acc[mt][nt][1],
                             acc[mt][nt][2], acc[mt][nt][3],
                             a[mt][0], a[mt][1], a[mt][2], a[mt][3], b0, b1);
            }
        }
        cp_wait0();
        __syncthreads();
    }

#pragma unroll
    for (int mt = 0; mt < MT; mt++) {
        int dA = d0 + mb + mt * 16 + lr;
        float bA = bias[dA], bB = bias[dA + 8];
        if (OUTM == 1) {
            float* op = (float*)outp;
#pragma unroll
            for (int nt = 0; nt < NTl; nt++) {
                int nc = n0 + nb + nt * 8 + 2 * lc;
                float* o = op + ((size_t)b * NN + nc) * DQK;
                o[dA]           = tf32r(acc[mt][nt][0] + bA);
                o[DQK + dA]     = tf32r(acc[mt][nt][1] + bA);
                o[dA + 8]       = tf32r(acc[mt][nt][2] + bB);
                o[DQK + dA + 8] = tf32r(acc[mt][nt][3] + bB);
            }
        } else if (OUTM == 2) {
            float* oA = (float*)outp + ((size_t)b * dout_total + dA) * NN + n0 + nb;
            float* oB = oA + (size_t)8 * NN;
#pragma unroll
            for (int nt = 0; nt < NTl; nt++) {
                int col = nt * 8 + 2 * lc;
                *(float2*)&oA[col] = make_float2(tf32r(acc[mt][nt][0] + bA),
                                                tf32r(acc[mt][nt][1] + bA));
                *(float2*)&oB[col] = make_float2(tf32r(acc[mt][nt][2] + bB),
                                                tf32r(acc[mt][nt][3] + bB));
            }
        } else {
            __nv_bfloat16* oA = (__nv_bfloat16*)outp
                + ((size_t)b * dout_total + dA) * NN + n0 + nb;
            __nv_bfloat16* oB = oA + (size_t)8 * NN;
#pragma unroll
            for (int nt = 0; nt < NTl; nt++) {
                int col = nt * 8 + 2 * lc;
                *(__nv_bfloat162*)&oA[col] =
                    __floats2bfloat162_rn(acc[mt][nt][0] + bA, acc[mt][nt][1] + bA);
                *(__nv_bfloat162*)&oB[col] =
                    __floats2bfloat162_rn(acc[mt][nt][2] + bB, acc[mt][nt][3] + bB);
            }
        }
    }
}

// ---------------- flash attention: tf32 S + bf16 PV, BN=64 -----------------
// BM=128 rows/CTA, BN=64 KV cols/iter, 512 threads (16 warps).
// S: 8 row-groups x 2 col-HALVES (16 rows x 32 cols per warp, scol offset);
// each half accumulates its own 32-col partial sum; epilogue adds halves.
// PV: 4 row-groups x 4 ch-groups (32 rows x 64 ch per warp), bf16, kk<4.
// Q fragments hoisted into registers (iteration-invariant).
// K,V double-buffered cp.async; P single-buffered. Two barriers per iter.
#define BM 128
#define BN 64
#define QSTR 36     // floats
#define KSTR 72     // floats
#define VSTRB 72    // bf16 elements (64 data + 8 pad; 144B rows)
#define PSTRB 72    // bf16 elements

#define KSLOT 9216      // 32*72*4 bytes
#define VSLOT 36864     // 256*72*2 bytes
#define PSLOT 18432     // 128*72*2 bytes

#define OFF_QS 0                              // 128*36*4 = 18432
#define OFF_K  18432                          // 2*KSLOT  = 18432
#define OFF_V  36864                          // 2*VSLOT  = 73728
#define OFF_P  110592                         // 1*PSLOT  = 18432
#define OFF_L  129024                         // 2*128*4  = 1024
#define ATT_SMEM 130048

__global__ __launch_bounds__(512, 1) void attn_kernel(
    const float* __restrict__ qT, const float* __restrict__ k,
    const __nv_bfloat16* __restrict__ v, const float* __restrict__ query,
    const float* __restrict__ gamma, float* __restrict__ outp)
{
    extern __shared__ char smem[];
    float*         qs = (float*)(smem + OFF_QS);
    float*         ks = (float*)(smem + OFF_K);
    __nv_bfloat16* vs = (__nv_bfloat16*)(smem + OFF_V);
    __nv_bfloat16* ps = (__nv_bfloat16*)(smem + OFF_P);
    float*         lp = (float*)(smem + OFF_L);

    int tid  = threadIdx.x;
    int warp = tid >> 5;
    int lane = tid & 31;
    int lr = lane >> 2, lc = lane & 3;
    int b  = blockIdx.y;
    int i0 = blockIdx.x * BM;

    // S-phase mapping: 8 row-groups x 2 col-halves (16 rows x 32 cols/warp)
    int srow  = (warp & 7) * 16;
    int chalf = warp >> 3;
    int scol  = chalf * 32;
    // PV-phase mapping: 4 row-groups x 4 channel-groups (32 rows x 64 ch/warp)
    int pvrow = (warp & 3) * 32;
    int cb    = (warp >> 2) * 64;

    const float*         qTb = qT + ((size_t)b * NN + i0) * DQK;
    const float*         kb  = k  + (size_t)b * DQK * NN;
    const __nv_bfloat16* vb  = v  + (size_t)b * CQi * NN;

    auto prefetchKV = [&](int m0, int pb) {
        // K tile [32 d][64 j] f32: 512 chunks of 16B
        {
            int d = tid >> 4, ch = tid & 15;
            cp16p((char*)ks + pb * KSLOT + d * (KSTR * 4) + ch * 16,
                  kb + (size_t)d * NN + m0 + ch * 4);
        }
        // V tile [256 c][64 j] bf16: 2048 chunks of 16B
#pragma unroll
        for (int it = 0; it < 4; it++) {
            int idx = tid + it * 512;
            int c = idx >> 3, ch = idx & 7;
            cp16p((char*)vs + pb * VSLOT + c * (VSTRB * 2) + ch * 16,
                  vb + (size_t)c * NN + m0 + ch * 8);
        }
    };

    // ---- prolog: load Q tile [128 rows][32 d] + K(0),V(0) ----
#pragma unroll
    for (int it = 0; it < 2; it++) {
        int idx = tid + it * 512;
        int i = idx >> 3, ch = idx & 7;
        cp16p((char*)qs + i * (QSTR * 4) + ch * 16, qTb + i * DQK + ch * 4);
    }
    prefetchKV(0, 0);
    cp_commit();
    cp_wait0();
    __syncthreads();

    // ---- hoist Q fragments (iteration-invariant) ----
    uint32 qa[4][4];
#pragma unroll
    for (int kk = 0; kk < 4; kk++) {
        const float* ar = qs + (srow + lr) * QSTR + kk * 8 + lc;
        qa[kk][0] = __float_as_uint(ar[0]);
        qa[kk][1] = __float_as_uint(ar[8 * QSTR]);
        qa[kk][2] = __float_as_uint(ar[4]);
        qa[kk][3] = __float_as_uint(ar[8 * QSTR + 4]);
    }

    float lsum0 = 0.f, lsum1 = 0.f;
    float acc[2][8][4];
#pragma unroll
    for (int mt = 0; mt < 2; mt++)
#pragma unroll
        for (int nt = 0; nt < 8; nt++)
#pragma unroll
            for (int i = 0; i < 4; i++) acc[mt][nt][i] = 0.f;

    const int NIT = NN / BN;   // 64

    for (int t = 0; t < NIT; t++) {
        int buf = t & 1;
        if (t + 1 < NIT) { prefetchKV((t + 1) * BN, buf ^ 1); cp_commit(); }

        // ---- S = Q K^T (tf32): 16 rows x 32 cols per warp (own half) ----
        float sc[4][4];
#pragma unroll
        for (int nt = 0; nt < 4; nt++)
#pragma unroll
            for (int i = 0; i < 4; i++) sc[nt][i] = 0.f;

        const float* ksB = (const float*)((char*)ks + buf * KSLOT);
#pragma unroll
        for (int kk = 0; kk < 4; kk++) {
            const float* br = ksB + (kk * 8 + lc) * KSTR + scol + lr;
#pragma unroll
            for (int nt = 0; nt < 4; nt++) {
                uint32 b0 = __float_as_uint(br[nt * 8]);
                uint32 b1 = __float_as_uint(br[4 * KSTR + nt * 8]);
                mma_tf32(sc[nt][0], sc[nt][1], sc[nt][2], sc[nt][3],
                         qa[kk][0], qa[kk][1], qa[kk][2], qa[kk][3], b0, b1);
            }
        }

        // ---- exp in registers (bf16 P), half-row sums from rounded p ----
#pragma unroll
        for (int nt = 0; nt < 4; nt++) {
            float p0 = __expf(sc[nt][0]);
            float p1 = __expf(sc[nt][1]);
            float p2 = __expf(sc[nt][2]);
            float p3 = __expf(sc[nt][3]);
            __nv_bfloat162 h0 = __floats2bfloat162_rn(p0, p1);
            __nv_bfloat162 h1 = __floats2bfloat162_rn(p2, p3);
            float2 r0f = __bfloat1622float2(h0);
            float2 r1f = __bfloat1622float2(h1);
            lsum0 += r0f.x + r0f.y;
            lsum1 += r1f.x + r1f.y;
            int col = scol + nt * 8 + 2 * lc;
            *(__nv_bfloat162*)&ps[(srow + lr) * PSTRB + col]     = h0;
            *(__nv_bfloat162*)&ps[(srow + lr + 8) * PSTRB + col] = h1;
        }
        __syncthreads();   // P visible to all

        // ---- PV: acc += P V (bf16), 32 rows x 64 ch per warp, kk<4 ----
        const __nv_bfloat16* vsB = (const __nv_bfloat16*)((char*)vs + buf * VSLOT);
#pragma unroll
        for (int kk = 0; kk < 4; kk++) {
            uint32 a[2][4];
#pragma unroll
            for (int mt = 0; mt < 2; mt++) {
                const __nv_bfloat16* ar =
                    ps + (pvrow + mt * 16 + lr) * PSTRB + kk * 16 + 2 * lc;
                a[mt][0] = *(const uint32*)(ar);
                a[mt][1] = *(const uint32*)(ar + 8 * PSTRB);
                a[mt][2] = *(const uint32*)(ar + 8);
                a[mt][3] = *(const uint32*)(ar + 8 * PSTRB + 8);
            }
#pragma unroll
            for (int nt = 0; nt < 8; nt++) {
                const __nv_bfloat16* br =
                    vsB + (cb + nt * 8 + lr) * VSTRB + kk * 16 + 2 * lc;
                uint32 b0 = *(const uint32*)(br);
                uint32 b1 = *(const uint32*)(br + 8);
#pragma unroll
                for (int mt = 0; mt < 2; mt++)
                    mma_bf16(acc[mt][nt][0], acc[mt][nt][1],
                             acc[mt][nt][2], acc[mt][nt][3],
                             a[mt][0], a[mt][1], a[mt][2], a[mt][3], b0, b1);
            }
        }
        cp_wait0();
        __syncthreads();   // PV done (P reusable) + next K/V tiles arrived
    }

    // ---- half-row-sum reduction across the quad; halves stored separately --
    lsum0 += __shfl_xor_sync(0xffffffffu, lsum0, 1);
    lsum0 += __shfl_xor_sync(0xffffffffu, lsum0, 2);
    lsum1 += __shfl_xor_sync(0xffffffffu, lsum1, 1);
    lsum1 += __shfl_xor_sync(0xffffffffu, lsum1, 2);
    if (lc == 0) {
        lp[chalf * BM + srow + lr]     = lsum0;
        lp[chalf * BM + srow + lr + 8] = lsum1;
    }
    __syncthreads();

    // ---- epilogue: out = gamma * acc / l + query ----
    float gm = gamma[0];
    const float* qry = query + (size_t)b * CQi * NN + i0;
    float*       ob  = outp  + (size_t)b * CQi * NN + i0;
#pragma unroll
    for (int mt = 0; mt < 2; mt++) {
        int r0 = pvrow + mt * 16 + lr;
        int r1 = r0 + 8;
        float f0 = gm / (lp[r0] + lp[BM + r0]);
        float f1 = gm / (lp[r1] + lp[BM + r1]);
#pragma unroll
        for (int nt = 0; nt < 8; nt++) {
            int c = cb + nt * 8 + 2 * lc;
            size_t o00 = (size_t)c * NN + r0;
            size_t o01 = (size_t)(c + 1) * NN + r0;
            size_t o10 = (size_t)c * NN + r1;
            size_t o11 = (size_t)(c + 1) * NN + r1;
            ob[o00] = f0 * acc[mt][nt][0] + qry[o00];
            ob[o01] = f0 * acc[mt][nt][1] + qry[o01];
            ob[o10] = f1 * acc[mt][nt][2] + qry[o10];
            ob[o11] = f1 * acc[mt][nt][3] + qry[o11];
        }
    }
}

// ---------------- host launcher -------------------------------------------
extern "C" void kernel_launch(void* const* d_in, const int* in_sizes, int n_in,
                              void* d_out, int out_size)
{
    const float* query     = (const float*)d_in[0];
    const float* key_value = (const float*)d_in[1];
    const float* Wq = (const float*)d_in[2];
    const float* bq = (const float*)d_in[3];
    const float* Wk = (const float*)d_in[4];
    const float* bk = (const float*)d_in[5];
    const float* Wv = (const float*)d_in[6];
    const float* bv = (const float*)d_in[7];
    const float* gamma = (const float*)d_in[8];
    float* out = (float*)d_out;

    void* p;
    cudaGetSymbolAddress(&p, g_kv); float*         kvb  = (float*)p;
    cudaGetSymbolAddress(&p, g_q);  float*         qb   = (float*)p;
    cudaGetSymbolAddress(&p, g_k);  float*         kb   = (float*)p;
    cudaGetSymbolAddress(&p, g_v);  __nv_bfloat16* vbuf = (__nv_bfloat16*)p;

    // 1) bilinear upsample
    resize_kernel<<<(BQ * CKV * NN + 255) / 256, 256>>>(key_value);

    // 2) projections: Q -> tf32 transposed, K -> tf32 [d][n], V -> bf16 [d][n]
    {
        size_t smQ = (2 * 32 * 260 + 2 * 32 * 36) * sizeof(float);
        size_t smV = (2 * 32 * 132 + 2 * 128 * 36) * sizeof(float);
        cudaFuncSetAttribute(proj_mma<256, 32, 256, 16, 64, 1>,
                             cudaFuncAttributeMaxDynamicSharedMemorySize, (int)smQ);
        cudaFuncSetAttribute(proj_mma<512, 32, 256, 16, 64, 2>,
                             cudaFuncAttributeMaxDynamicSharedMemorySize, (int)smQ);
        cudaFuncSetAttribute(proj_mma<512, 128, 128, 32, 64, 3>,
                             cudaFuncAttributeMaxDynamicSharedMemorySize, (int)smV);
        proj_mma<256, 32, 256, 16, 64, 1><<<dim3(16, 8, 1), 256, smQ>>>(query, Wq, bq, qb, 32);
        proj_mma<512, 32, 256, 16, 64, 2><<<dim3(16, 8, 1), 256, smQ>>>(kvb, Wk, bk, kb, 32);
        proj_mma<512, 128, 128, 32, 64, 3><<<dim3(32, 8, 2), 256, smV>>>(kvb, Wv, bv, vbuf, 256);
    }

    // 3) flash attention + residual
    cudaFuncSetAttribute(attn_kernel, cudaFuncAttributeMaxDynamicSharedMemorySize,
                         ATT_SMEM);
    attn_kernel<<<dim3(NN / BM, BQ), 512, ATT_SMEM>>>(qb, kb, vbuf, query,
                                                      gamma, out);
}

// round 13
// speedup vs baseline: 1.2059x; 1.0267x over previous
#include <cuda_runtime.h>
#include <cuda_bf16.h>
#include <cstdint>

// Problem constants
#define BQ   8
#define CQi  256
#define CKV  512
#define NN   4096
#define DQK  32

typedef unsigned long long ull;
typedef unsigned int uint32;

// ---------------- scratch (static device globals; no allocations) ----------
__device__ float          g_kv[BQ * CKV * NN];  // resized key_value [b][c][n]
__device__ float          g_q [BQ * NN * DQK];  // Q^T [b][n][d] (tf32-rounded)
__device__ float          g_k [BQ * DQK * NN];  // K   [b][d][n] (tf32-rounded)
__device__ __nv_bfloat16  g_v [BQ * CQi * NN];  // V   [b][c][n] (bf16)

// ---------------- helpers ---------------------------------------------------
__device__ __forceinline__ float tf32r(float x) {
    uint32 u;
    asm("cvt.rna.tf32.f32 %0, %1;" : "=r"(u) : "f"(x));
    return __uint_as_float(u);
}
__device__ __forceinline__ void mma_tf32(
    float& c0, float& c1, float& c2, float& c3,
    uint32 a0, uint32 a1, uint32 a2, uint32 a3,
    uint32 b0, uint32 b1)
{
    asm volatile(
        "mma.sync.aligned.m16n8k8.row.col.f32.tf32.tf32.f32 "
        "{%0,%1,%2,%3}, {%4,%5,%6,%7}, {%8,%9}, {%0,%1,%2,%3};"
        : "+f"(c0), "+f"(c1), "+f"(c2), "+f"(c3)
        : "r"(a0), "r"(a1), "r"(a2), "r"(a3), "r"(b0), "r"(b1));
}
__device__ __forceinline__ void mma_bf16(
    float& c0, float& c1, float& c2, float& c3,
    uint32 a0, uint32 a1, uint32 a2, uint32 a3,
    uint32 b0, uint32 b1)
{
    asm volatile(
        "mma.sync.aligned.m16n8k16.row.col.f32.bf16.bf16.f32 "
        "{%0,%1,%2,%3}, {%4,%5,%6,%7}, {%8,%9}, {%0,%1,%2,%3};"
        : "+f"(c0), "+f"(c1), "+f"(c2), "+f"(c3)
        : "r"(a0), "r"(a1), "r"(a2), "r"(a3), "r"(b0), "r"(b1));
}
__device__ __forceinline__ void ldsm_x4(uint32& r0, uint32& r1, uint32& r2,
                                        uint32& r3, uint32 addr)
{
    asm volatile(
        "ldmatrix.sync.aligned.m8n8.x4.shared.b16 {%0,%1,%2,%3}, [%4];"
        : "=r"(r0), "=r"(r1), "=r"(r2), "=r"(r3) : "r"(addr));
}
__device__ __forceinline__ void cp16p(void* sdst, const void* gsrc) {
    uint32 s = (uint32)__cvta_generic_to_shared(sdst);
    asm volatile("cp.async.cg.shared.global [%0], [%1], 16;" :: "r"(s), "l"(gsrc));
}
__device__ __forceinline__ void cp_commit() {
    asm volatile("cp.async.commit_group;" ::: "memory");
}
__device__ __forceinline__ void cp_wait0() {
    asm volatile("cp.async.wait_group 0;" ::: "memory");
}

// ---------------- bilinear 2x upsample (half-pixel, clamped) ---------------
__global__ void resize_kernel(const float* __restrict__ src) {
    int idx = blockIdx.x * 256 + threadIdx.x;
    if (idx >= BQ * CKV * NN) return;
    int x  = idx & 63;
    int y  = (idx >> 6) & 63;
    int cb = idx >> 12;
    float fx = 0.5f * (float)x - 0.25f;
    float fy = 0.5f * (float)y - 0.25f;
    float fx0 = floorf(fx), fy0 = floorf(fy);
    float wx = fx - fx0, wy = fy - fy0;
    int x0 = max((int)fx0, 0), x1 = min((int)fx0 + 1, 31);
    int y0 = max((int)fy0, 0), y1 = min((int)fy0 + 1, 31);
    const float* s = src + (size_t)cb * 1024;
    float v00 = s[y0 * 32 + x0], v01 = s[y0 * 32 + x1];
    float v10 = s[y1 * 32 + x0], v11 = s[y1 * 32 + x1];
    float top = v00 + wx * (v01 - v00);
    float bot = v10 + wx * (v11 - v10);
    g_kv[idx] = top + wy * (bot - top);
}

// ---------------- tf32-mma 1x1 conv GEMM -----------------------------------
// OUTM: 1 = tf32 transposed [n][DQK] (Q), 2 = tf32 [d][n] f32 (K),
//       3 = bf16 [d][n] (V)
template <int CIN, int DT, int NT, int WM, int WN, int OUTM>
__global__ __launch_bounds__(256) void proj_mma(
    const float* __restrict__ in, const float* __restrict__ W,
    const float* __restrict__ bias, void* __restrict__ outp, int dout_total)
{
    constexpr int BK  = 32;
    constexpr int NTP = NT + 4;
    constexpr int WSP = 36;
    constexpr int KCH = CIN / BK;
    constexpr int MT  = WM / 16;
    constexpr int NTl = WN / 8;
    constexpr int WARPS_N = NT / WN;

    extern __shared__ float smx[];
    float* ins = smx;
    float* Ws  = smx + 2 * BK * NTP;

    int tid  = threadIdx.x;
    int warp = tid >> 5, lane = tid & 31;
    int lr = lane >> 2, lc = lane & 3;
    int nwarp = warp % WARPS_N, mwarp = warp / WARPS_N;
    int mb = mwarp * WM, nb = nwarp * WN;

    int b  = blockIdx.y;
    int n0 = blockIdx.x * NT;
    int d0 = blockIdx.z * DT;

    const float* inb = in + (size_t)b * CIN * NN + n0;

    float acc[MT][NTl][4];
#pragma unroll
    for (int mt = 0; mt < MT; mt++)
#pragma unroll
        for (int nt = 0; nt < NTl; nt++)
#pragma unroll
            for (int i = 0; i < 4; i++) acc[mt][nt][i] = 0.f;

    auto prefetch = [&](int kc, int pb) {
        float* insB = ins + pb * BK * NTP;
        float* WsB  = Ws  + pb * DT * WSP;
        constexpr int INIT = BK * NT / 4 / 256;
#pragma unroll
        for (int it = 0; it < INIT; it++) {
            int idx = tid + it * 256;
            int c = idx / (NT / 4), j4 = (idx % (NT / 4)) * 4;
            cp16p(insB + c * NTP + j4, inb + (size_t)(kc * BK + c) * NN + j4);
        }
        constexpr int WIT = DT * 8 / 256;
#pragma unroll
        for (int it = 0; it < (WIT > 0 ? WIT : 1); it++) {
            int idx = tid + it * 256;
            if (idx < DT * 8) {
                int d = idx >> 3, cj = (idx & 7) * 4;
                cp16p(WsB + d * WSP + cj, W + (size_t)(d0 + d) * CIN + kc * BK + cj);
            }
        }
    };

    prefetch(0, 0);
    cp_commit();
    cp_wait0();
    __syncthreads();

    for (int kc = 0; kc < KCH; kc++) {
        int buf = kc & 1;
        if (kc + 1 < KCH) { prefetch(kc + 1, buf ^ 1); cp_commit(); }
        const float* insB = ins + buf * BK * NTP;
        const float* WsB  = Ws  + buf * DT * WSP;
#pragma unroll
        for (int kk = 0; kk < 4; kk++) {
            uint32 a[MT][4];
#pragma unroll
            for (int mt = 0; mt < MT; mt++) {
                const float* ar = WsB + (mb + mt * 16 + lr) * WSP + kk * 8 + lc;
                a[mt][0] = __float_as_uint(ar[0]);
                a[mt][1] = __float_as_uint(ar[8 * WSP]);
                a[mt][2] = __float_as_uint(ar[4]);
                a[mt][3] = __float_as_uint(ar[8 * WSP + 4]);
            }
            const float* br = insB + (kk * 8 + lc) * NTP + nb + lr;
#pragma unroll
            for (int nt = 0; nt < NTl; nt++) {
                uint32 b0 = __float_as_uint(br[nt * 8]);
                uint32 b1 = __float_as_uint(br[4 * NTP + nt * 8]);
#pragma unroll
                for (int mt = 0; mt < MT; mt++)
                    mma_tf32(acc[mt][nt][0], acc[mt][nt][1],
                             acc[mt][nt][2], acc[mt][nt][3],
                             a[mt][0], a[mt][1], a[mt][2], a[mt][3], b0, b1);
            }
        }
        cp_wait0();
        __syncthreads();
    }

#pragma unroll
    for (int mt = 0; mt < MT; mt++) {
        int dA = d0 + mb + mt * 16 + lr;
        float bA = bias[dA], bB = bias[dA + 8];
        if (OUTM == 1) {
            float* op = (float*)outp;
#pragma unroll
            for (int nt = 0; nt < NTl; nt++) {
                int nc = n0 + nb + nt * 8 + 2 * lc;
                float* o = op + ((size_t)b * NN + nc) * DQK;
                o[dA]           = tf32r(acc[mt][nt][0] + bA);
                o[DQK + dA]     = tf32r(acc[mt][nt][1] + bA);
                o[dA + 8]       = tf32r(acc[mt][nt][2] + bB);
                o[DQK + dA + 8] = tf32r(acc[mt][nt][3] + bB);
            }
        } else if (OUTM == 2) {
            float* oA = (float*)outp + ((size_t)b * dout_total + dA) * NN + n0 + nb;
            float* oB = oA + (size_t)8 * NN;
#pragma unroll
            for (int nt = 0; nt < NTl; nt++) {
                int col = nt * 8 + 2 * lc;
                *(float2*)&oA[col] = make_float2(tf32r(acc[mt][nt][0] + bA),
                                                tf32r(acc[mt][nt][1] + bA));
                *(float2*)&oB[col] = make_float2(tf32r(acc[mt][nt][2] + bB),
                                                tf32r(acc[mt][nt][3] + bB));
            }
        } else {
            __nv_bfloat16* oA = (__nv_bfloat16*)outp
                + ((size_t)b * dout_total + dA) * NN + n0 + nb;
            __nv_bfloat16* oB = oA + (size_t)8 * NN;
#pragma unroll
            for (int nt = 0; nt < NTl; nt++) {
                int col = nt * 8 + 2 * lc;
                *(__nv_bfloat162*)&oA[col] =
                    __floats2bfloat162_rn(acc[mt][nt][0] + bA, acc[mt][nt][1] + bA);
                *(__nv_bfloat162*)&oB[col] =
                    __floats2bfloat162_rn(acc[mt][nt][2] + bB, acc[mt][nt][3] + bB);
            }
        }
    }
}

// ---------------- flash attention: tf32 S + bf16 PV, BN=64, LDSM -----------
// Identical to the R12 kernel except PV fragment loads use ldmatrix.x4.
#define BM 128
#define BN 64
#define QSTR 36     // floats
#define KSTR 72     // floats
#define VSTRB 72    // bf16 elements (64 data + 8 pad; 144B rows)
#define PSTRB 72    // bf16 elements

#define KSLOT 9216      // 32*72*4 bytes
#define VSLOT 36864     // 256*72*2 bytes
#define PSLOT 18432     // 128*72*2 bytes

#define OFF_QS 0                              // 128*36*4 = 18432
#define OFF_K  18432                          // 2*KSLOT  = 18432
#define OFF_V  36864                          // 2*VSLOT  = 73728
#define OFF_P  110592                         // 1*PSLOT  = 18432
#define OFF_L  129024                         // 2*128*4  = 1024
#define ATT_SMEM 130048

__global__ __launch_bounds__(512, 1) void attn_kernel(
    const float* __restrict__ qT, const float* __restrict__ k,
    const __nv_bfloat16* __restrict__ v, const float* __restrict__ query,
    const float* __restrict__ gamma, float* __restrict__ outp)
{
    extern __shared__ char smem[];
    uint32 sb = (uint32)__cvta_generic_to_shared(smem);
    float*         qs = (float*)(smem + OFF_QS);
    float*         ks = (float*)(smem + OFF_K);
    __nv_bfloat16* vs = (__nv_bfloat16*)(smem + OFF_V);
    __nv_bfloat16* ps = (__nv_bfloat16*)(smem + OFF_P);
    float*         lp = (float*)(smem + OFF_L);

    int tid  = threadIdx.x;
    int warp = tid >> 5;
    int lane = tid & 31;
    int lr = lane >> 2, lc = lane & 3;
    int b  = blockIdx.y;
    int i0 = blockIdx.x * BM;

    // S-phase mapping: 8 row-groups x 2 col-halves (16 rows x 32 cols/warp)
    int srow  = (warp & 7) * 16;
    int chalf = warp >> 3;
    int scol  = chalf * 32;
    // PV-phase mapping: 4 row-groups x 4 channel-groups (32 rows x 64 ch/warp)
    int pvrow = (warp & 3) * 32;
    int cb    = (warp >> 2) * 64;

    const float*         qTb = qT + ((size_t)b * NN + i0) * DQK;
    const float*         kb  = k  + (size_t)b * DQK * NN;
    const __nv_bfloat16* vb  = v  + (size_t)b * CQi * NN;

    auto prefetchKV = [&](int m0, int pb) {
        // K tile [32 d][64 j] f32: 512 chunks of 16B
        {
            int d = tid >> 4, ch = tid & 15;
            cp16p((char*)ks + pb * KSLOT + d * (KSTR * 4) + ch * 16,
                  kb + (size_t)d * NN + m0 + ch * 4);
        }
        // V tile [256 c][64 j] bf16: 2048 chunks of 16B
#pragma unroll
        for (int it = 0; it < 4; it++) {
            int idx = tid + it * 512;
            int c = idx >> 3, ch = idx & 7;
            cp16p((char*)vs + pb * VSLOT + c * (VSTRB * 2) + ch * 16,
                  vb + (size_t)c * NN + m0 + ch * 8);
        }
    };

    // ---- prolog: load Q tile [128 rows][32 d] + K(0),V(0) ----
#pragma unroll
    for (int it = 0; it < 2; it++) {
        int idx = tid + it * 512;
        int i = idx >> 3, ch = idx & 7;
        cp16p((char*)qs + i * (QSTR * 4) + ch * 16, qTb + i * DQK + ch * 4);
    }
    prefetchKV(0, 0);
    cp_commit();
    cp_wait0();
    __syncthreads();

    // ---- hoist Q fragments (iteration-invariant) ----
    uint32 qa[4][4];
#pragma unroll
    for (int kk = 0; kk < 4; kk++) {
        const float* ar = qs + (srow + lr) * QSTR + kk * 8 + lc;
        qa[kk][0] = __float_as_uint(ar[0]);
        qa[kk][1] = __float_as_uint(ar[8 * QSTR]);
        qa[kk][2] = __float_as_uint(ar[4]);
        qa[kk][3] = __float_as_uint(ar[8 * QSTR + 4]);
    }

    // ---- LDSM base addresses (bytes, iteration-invariant parts) ----
    // A (P): lane -> row pvrow+(lane&15), kcol offset ((lane>>1)&8)
    uint32 pA = sb + OFF_P
              + 2u * ((uint32)(pvrow + (lane & 15)) * PSTRB + ((lane >> 1) & 8));
    // B (V): lane -> row cb+(lane&7)+((lane>>1)&8), kcol offset (lane&8)
    uint32 pBrel = 2u * ((uint32)(cb + (lane & 7) + ((lane >> 1) & 8)) * VSTRB
                         + (lane & 8));

    float lsum0 = 0.f, lsum1 = 0.f;
    float acc[2][8][4];
#pragma unroll
    for (int mt = 0; mt < 2; mt++)
#pragma unroll
        for (int nt = 0; nt < 8; nt++)
#pragma unroll
            for (int i = 0; i < 4; i++) acc[mt][nt][i] = 0.f;

    const int NIT = NN / BN;   // 64

    for (int t = 0; t < NIT; t++) {
        int buf = t & 1;
        if (t + 1 < NIT) { prefetchKV((t + 1) * BN, buf ^ 1); cp_commit(); }

        // ---- S = Q K^T (tf32): 16 rows x 32 cols per warp (own half) ----
        float sc[4][4];
#pragma unroll
        for (int nt = 0; nt < 4; nt++)
#pragma unroll
            for (int i = 0; i < 4; i++) sc[nt][i] = 0.f;

        const float* ksB = (const float*)((char*)ks + buf * KSLOT);
#pragma unroll
        for (int kk = 0; kk < 4; kk++) {
            const float* br = ksB + (kk * 8 + lc) * KSTR + scol + lr;
#pragma unroll
            for (int nt = 0; nt < 4; nt++) {
                uint32 b0 = __float_as_uint(br[nt * 8]);
                uint32 b1 = __float_as_uint(br[4 * KSTR + nt * 8]);
                mma_tf32(sc[nt][0], sc[nt][1], sc[nt][2], sc[nt][3],
                         qa[kk][0], qa[kk][1], qa[kk][2], qa[kk][3], b0, b1);
            }
        }

        // ---- exp in registers (bf16 P), half-row sums from rounded p ----
#pragma unroll
        for (int nt = 0; nt < 4; nt++) {
            float p0 = __expf(sc[nt][0]);
            float p1 = __expf(sc[nt][1]);
            float p2 = __expf(sc[nt][2]);
            float p3 = __expf(sc[nt][3]);
            __nv_bfloat162 h0 = __floats2bfloat162_rn(p0, p1);
            __nv_bfloat162 h1 = __floats2bfloat162_rn(p2, p3);
            float2 r0f = __bfloat1622float2(h0);
            float2 r1f = __bfloat1622float2(h1);
            lsum0 += r0f.x + r0f.y;
            lsum1 += r1f.x + r1f.y;
            int col = scol + nt * 8 + 2 * lc;
            *(__nv_bfloat162*)&ps[(srow + lr) * PSTRB + col]     = h0;
            *(__nv_bfloat162*)&ps[(srow + lr + 8) * PSTRB + col] = h1;
        }
        __syncthreads();   // P visible to all

        // ---- PV: acc += P V (bf16) via ldmatrix fragments ----
        uint32 pB = sb + OFF_V + (uint32)buf * VSLOT + pBrel;
#pragma unroll
        for (int kk = 0; kk < 4; kk++) {
            uint32 a[2][4];
#pragma unroll
            for (int mt = 0; mt < 2; mt++)
                ldsm_x4(a[mt][0], a[mt][1], a[mt][2], a[mt][3],
                        pA + 2u * ((uint32)mt * 16 * PSTRB + (uint32)kk * 16));
#pragma unroll
            for (int ntp = 0; ntp < 4; ntp++) {
                uint32 b0, b1, b2, b3;
                ldsm_x4(b0, b1, b2, b3,
                        pB + 2u * ((uint32)ntp * 16 * VSTRB + (uint32)kk * 16));
#pragma unroll
                for (int mt = 0; mt < 2; mt++) {
                    mma_bf16(acc[mt][2 * ntp][0],     acc[mt][2 * ntp][1],
                             acc[mt][2 * ntp][2],     acc[mt][2 * ntp][3],
                             a[mt][0], a[mt][1], a[mt][2], a[mt][3], b0, b1);
                    mma_bf16(acc[mt][2 * ntp + 1][0], acc[mt][2 * ntp + 1][1],
                             acc[mt][2 * ntp + 1][2], acc[mt][2 * ntp + 1][3],
                             a[mt][0], a[mt][1], a[mt][2], a[mt][3], b2, b3);
                }
            }
        }
        cp_wait0();
        __syncthreads();   // PV done (P reusable) + next K/V tiles arrived
    }

    // ---- half-row-sum reduction across the quad; halves stored separately --
    lsum0 += __shfl_xor_sync(0xffffffffu, lsum0, 1);
    lsum0 += __shfl_xor_sync(0xffffffffu, lsum0, 2);
    lsum1 += __shfl_xor_sync(0xffffffffu, lsum1, 1);
    lsum1 += __shfl_xor_sync(0xffffffffu, lsum1, 2);
    if (lc == 0) {
        lp[chalf * BM + srow + lr]     = lsum0;
        lp[chalf * BM + srow + lr + 8] = lsum1;
    }
    __syncthreads();

    // ---- epilogue: out = gamma * acc / l + query ----
    float gm = gamma[0];
    const float* qry = query + (size_t)b * CQi * NN + i0;
    float*       ob  = outp  + (size_t)b * CQi * NN + i0;
#pragma unroll
    for (int mt = 0; mt < 2; mt++) {
        int r0 = pvrow + mt * 16 + lr;
        int r1 = r0 + 8;
        float f0 = gm / (lp[r0] + lp[BM + r0]);
        float f1 = gm / (lp[r1] + lp[BM + r1]);
#pragma unroll
        for (int nt = 0; nt < 8; nt++) {
            int c = cb + nt * 8 + 2 * lc;
            size_t o00 = (size_t)c * NN + r0;
            size_t o01 = (size_t)(c + 1) * NN + r0;
            size_t o10 = (size_t)c * NN + r1;
            size_t o11 = (size_t)(c + 1) * NN + r1;
            ob[o00] = f0 * acc[mt][nt][0] + qry[o00];
            ob[o01] = f0 * acc[mt][nt][1] + qry[o01];
            ob[o10] = f1 * acc[mt][nt][2] + qry[o10];
            ob[o11] = f1 * acc[mt][nt][3] + qry[o11];
        }
    }
}

// ---------------- host launcher -------------------------------------------
extern "C" void kernel_launch(void* const* d_in, const int* in_sizes, int n_in,
                              void* d_out, int out_size)
{
    const float* query     = (const float*)d_in[0];
    const float* key_value = (const float*)d_in[1];
    const float* Wq = (const float*)d_in[2];
    const float* bq = (const float*)d_in[3];
    const float* Wk = (const float*)d_in[4];
    const float* bk = (const float*)d_in[5];
    const float* Wv = (const float*)d_in[6];
    const float* bv = (const float*)d_in[7];
    const float* gamma = (const float*)d_in[8];
    float* out = (float*)d_out;

    void* p;
    cudaGetSymbolAddress(&p, g_kv); float*         kvb  = (float*)p;
    cudaGetSymbolAddress(&p, g_q);  float*         qb   = (float*)p;
    cudaGetSymbolAddress(&p, g_k);  float*         kb   = (float*)p;
    cudaGetSymbolAddress(&p, g_v);  __nv_bfloat16* vbuf = (__nv_bfloat16*)p;

    // 1) bilinear upsample
    resize_kernel<<<(BQ * CKV * NN + 255) / 256, 256>>>(key_value);

    // 2) projections: Q -> tf32 transposed, K -> tf32 [d][n], V -> bf16 [d][n]
    {
        size_t smQ = (2 * 32 * 260 + 2 * 32 * 36) * sizeof(float);
        size_t smV = (2 * 32 * 132 + 2 * 128 * 36) * sizeof(float);
        cudaFuncSetAttribute(proj_mma<256, 32, 256, 16, 64, 1>,
                             cudaFuncAttributeMaxDynamicSharedMemorySize, (int)smQ);
        cudaFuncSetAttribute(proj_mma<512, 32, 256, 16, 64, 2>,
                             cudaFuncAttributeMaxDynamicSharedMemorySize, (int)smQ);
        cudaFuncSetAttribute(proj_mma<512, 128, 128, 32, 64, 3>,
                             cudaFuncAttributeMaxDynamicSharedMemorySize, (int)smV);
        proj_mma<256, 32, 256, 16, 64, 1><<<dim3(16, 8, 1), 256, smQ>>>(query, Wq, bq, qb, 32);
        proj_mma<512, 32, 256, 16, 64, 2><<<dim3(16, 8, 1), 256, smQ>>>(kvb, Wk, bk, kb, 32);
        proj_mma<512, 128, 128, 32, 64, 3><<<dim3(32, 8, 2), 256, smV>>>(kvb, Wv, bv, vbuf, 256);
    }

    // 3) flash attention + residual
    cudaFuncSetAttribute(attn_kernel, cudaFuncAttributeMaxDynamicSharedMemorySize,
                         ATT_SMEM);
    attn_kernel<<<dim3(NN / BM, BQ), 512, ATT_SMEM>>>(qb, kb, vbuf, query,
                                                      gamma, out);
}

// round 14
// speedup vs baseline: 1.4334x; 1.1887x over previous
#include <cuda_runtime.h>
#include <cuda_bf16.h>
#include <cstdint>

// Problem constants
#define BQ   8
#define CQi  256
#define CKV  512
#define NN   4096
#define DQK  32
#define NLOW 1024    // 32x32 low-res spatial

typedef unsigned long long ull;
typedef unsigned int uint32;

// ---------------- scratch (static device globals; no allocations) ----------
__device__ float          g_lo[BQ * (DQK + CQi) * NLOW]; // lowres K then V
__device__ float          g_q [BQ * NN * DQK];  // Q^T [b][n][d] (tf32-rounded)
__device__ float          g_k [BQ * DQK * NN];  // K   [b][d][n] (tf32-rounded)
__device__ __nv_bfloat16  g_v [BQ * CQi * NN];  // V   [b][c][n] (bf16)

// ---------------- helpers ---------------------------------------------------
__device__ __forceinline__ float tf32r(float x) {
    uint32 u;
    asm("cvt.rna.tf32.f32 %0, %1;" : "=r"(u) : "f"(x));
    return __uint_as_float(u);
}
__device__ __forceinline__ void mma_tf32(
    float& c0, float& c1, float& c2, float& c3,
    uint32 a0, uint32 a1, uint32 a2, uint32 a3,
    uint32 b0, uint32 b1)
{
    asm volatile(
        "mma.sync.aligned.m16n8k8.row.col.f32.tf32.tf32.f32 "
        "{%0,%1,%2,%3}, {%4,%5,%6,%7}, {%8,%9}, {%0,%1,%2,%3};"
        : "+f"(c0), "+f"(c1), "+f"(c2), "+f"(c3)
        : "r"(a0), "r"(a1), "r"(a2), "r"(a3), "r"(b0), "r"(b1));
}
__device__ __forceinline__ void mma_bf16(
    float& c0, float& c1, float& c2, float& c3,
    uint32 a0, uint32 a1, uint32 a2, uint32 a3,
    uint32 b0, uint32 b1)
{
    asm volatile(
        "mma.sync.aligned.m16n8k16.row.col.f32.bf16.bf16.f32 "
        "{%0,%1,%2,%3}, {%4,%5,%6,%7}, {%8,%9}, {%0,%1,%2,%3};"
        : "+f"(c0), "+f"(c1), "+f"(c2), "+f"(c3)
        : "r"(a0), "r"(a1), "r"(a2), "r"(a3), "r"(b0), "r"(b1));
}
__device__ __forceinline__ void ldsm_x4(uint32& r0, uint32& r1, uint32& r2,
                                        uint32& r3, uint32 addr)
{
    asm volatile(
        "ldmatrix.sync.aligned.m8n8.x4.shared.b16 {%0,%1,%2,%3}, [%4];"
        : "=r"(r0), "=r"(r1), "=r"(r2), "=r"(r3) : "r"(addr));
}
__device__ __forceinline__ void cp16p(void* sdst, const void* gsrc) {
    uint32 s = (uint32)__cvta_generic_to_shared(sdst);
    asm volatile("cp.async.cg.shared.global [%0], [%1], 16;" :: "r"(s), "l"(gsrc));
}
__device__ __forceinline__ void cp_commit() {
    asm volatile("cp.async.commit_group;" ::: "memory");
}
__device__ __forceinline__ void cp_wait0() {
    asm volatile("cp.async.wait_group 0;" ::: "memory");
}

// ---------------- bilinear 2x upsample (half-pixel, clamped) ---------------
// src: [cb][32*32] f32.  OUTMODE 0: f32 tf32-rounded; 1: bf16.
template <int OUTMODE>
__global__ void upsample_kernel(const float* __restrict__ src,
                                void* __restrict__ dst, int total)
{
    int idx = blockIdx.x * 256 + threadIdx.x;
    if (idx >= total) return;
    int x  = idx & 63;
    int y  = (idx >> 6) & 63;
    int cb = idx >> 12;
    float fx = 0.5f * (float)x - 0.25f;
    float fy = 0.5f * (float)y - 0.25f;
    float fx0 = floorf(fx), fy0 = floorf(fy);
    float wx = fx - fx0, wy = fy - fy0;
    int x0 = max((int)fx0, 0), x1 = min((int)fx0 + 1, 31);
    int y0 = max((int)fy0, 0), y1 = min((int)fy0 + 1, 31);
    const float* s = src + (size_t)cb * 1024;
    float v00 = s[y0 * 32 + x0], v01 = s[y0 * 32 + x1];
    float v10 = s[y1 * 32 + x0], v11 = s[y1 * 32 + x1];
    float top = v00 + wx * (v01 - v00);
    float bot = v10 + wx * (v11 - v10);
    float val = top + wy * (bot - top);
    if (OUTMODE == 0) ((float*)dst)[idx] = tf32r(val);
    else ((__nv_bfloat16*)dst)[idx] = __float2bfloat16(val);
}

// ---------------- tf32-mma 1x1 conv GEMM -----------------------------------
// nspat = spatial size of input AND output (dense [b][c][nspat]).
// OUTM: 0 = plain f32 [d][n], 1 = tf32 transposed [n][DQK] (Q)
template <int CIN, int DT, int NT, int WM, int WN, int OUTM>
__global__ __launch_bounds__(256) void proj_mma(
    const float* __restrict__ in, const float* __restrict__ W,
    const float* __restrict__ bias, void* __restrict__ outp,
    int dout_total, int nspat)
{
    constexpr int BK  = 32;
    constexpr int NTP = NT + 4;
    constexpr int WSP = 36;
    constexpr int KCH = CIN / BK;
    constexpr int MT  = WM / 16;
    constexpr int NTl = WN / 8;
    constexpr int WARPS_N = NT / WN;

    extern __shared__ float smx[];
    float* ins = smx;
    float* Ws  = smx + 2 * BK * NTP;

    int tid  = threadIdx.x;
    int warp = tid >> 5, lane = tid & 31;
    int lr = lane >> 2, lc = lane & 3;
    int nwarp = warp % WARPS_N, mwarp = warp / WARPS_N;
    int mb = mwarp * WM, nb = nwarp * WN;

    int b  = blockIdx.y;
    int n0 = blockIdx.x * NT;
    int d0 = blockIdx.z * DT;

    const float* inb = in + (size_t)b * CIN * nspat + n0;

    float acc[MT][NTl][4];
#pragma unroll
    for (int mt = 0; mt < MT; mt++)
#pragma unroll
        for (int nt = 0; nt < NTl; nt++)
#pragma unroll
            for (int i = 0; i < 4; i++) acc[mt][nt][i] = 0.f;

    auto prefetch = [&](int kc, int pb) {
        float* insB = ins + pb * BK * NTP;
        float* WsB  = Ws  + pb * DT * WSP;
        constexpr int INIT = BK * NT / 4 / 256;
#pragma unroll
        for (int it = 0; it < INIT; it++) {
            int idx = tid + it * 256;
            int c = idx / (NT / 4), j4 = (idx % (NT / 4)) * 4;
            cp16p(insB + c * NTP + j4, inb + (size_t)(kc * BK + c) * nspat + j4);
        }
        constexpr int WIT = DT * 8 / 256;
#pragma unroll
        for (int it = 0; it < (WIT > 0 ? WIT : 1); it++) {
            int idx = tid + it * 256;
            if (idx < DT * 8) {
                int d = idx >> 3, cj = (idx & 7) * 4;
                cp16p(WsB + d * WSP + cj, W + (size_t)(d0 + d) * CIN + kc * BK + cj);
            }
        }
    };

    prefetch(0, 0);
    cp_commit();
    cp_wait0();
    __syncthreads();

    for (int kc = 0; kc < KCH; kc++) {
        int buf = kc & 1;
        if (kc + 1 < KCH) { prefetch(kc + 1, buf ^ 1); cp_commit(); }
        const float* insB = ins + buf * BK * NTP;
        const float* WsB  = Ws  + buf * DT * WSP;
#pragma unroll
        for (int kk = 0; kk < 4; kk++) {
            uint32 a[MT][4];
#pragma unroll
            for (int mt = 0; mt < MT; mt++) {
                const float* ar = WsB + (mb + mt * 16 + lr) * WSP + kk * 8 + lc;
                a[mt][0] = __float_as_uint(ar[0]);
                a[mt][1] = __float_as_uint(ar[8 * WSP]);
                a[mt][2] = __float_as_uint(ar[4]);
                a[mt][3] = __float_as_uint(ar[8 * WSP + 4]);
            }
            const float* br = insB + (kk * 8 + lc) * NTP + nb + lr;
#pragma unroll
            for (int nt = 0; nt < NTl; nt++) {
                uint32 b0 = __float_as_uint(br[nt * 8]);
                uint32 b1 = __float_as_uint(br[4 * NTP + nt * 8]);
#pragma unroll
                for (int mt = 0; mt < MT; mt++)
                    mma_tf32(acc[mt][nt][0], acc[mt][nt][1],
                             acc[mt][nt][2], acc[mt][nt][3],
                             a[mt][0], a[mt][1], a[mt][2], a[mt][3], b0, b1);
            }
        }
        cp_wait0();
        __syncthreads();
    }

#pragma unroll
    for (int mt = 0; mt < MT; mt++) {
        int dA = d0 + mb + mt * 16 + lr;
        float bA = bias[dA], bB = bias[dA + 8];
        if (OUTM == 1) {
            float* op = (float*)outp;
#pragma unroll
            for (int nt = 0; nt < NTl; nt++) {
                int nc = n0 + nb + nt * 8 + 2 * lc;
                float* o = op + ((size_t)b * nspat + nc) * DQK;
                o[dA]           = tf32r(acc[mt][nt][0] + bA);
                o[DQK + dA]     = tf32r(acc[mt][nt][1] + bA);
                o[dA + 8]       = tf32r(acc[mt][nt][2] + bB);
                o[DQK + dA + 8] = tf32r(acc[mt][nt][3] + bB);
            }
        } else {
            float* oA = (float*)outp + ((size_t)b * dout_total + dA) * nspat + n0 + nb;
            float* oB = oA + (size_t)8 * nspat;
#pragma unroll
            for (int nt = 0; nt < NTl; nt++) {
                int col = nt * 8 + 2 * lc;
                *(float2*)&oA[col] = make_float2(acc[mt][nt][0] + bA,
                                                acc[mt][nt][1] + bA);
                *(float2*)&oB[col] = make_float2(acc[mt][nt][2] + bB,
                                                acc[mt][nt][3] + bB);
            }
        }
    }
}

// ---------------- flash attention: tf32 S + bf16 PV, BN=64, LDSM -----------
// Byte-identical to the R13 kernel.
#define BM 128
#define BN 64
#define QSTR 36     // floats
#define KSTR 72     // floats
#define VSTRB 72    // bf16 elements (64 data + 8 pad; 144B rows)
#define PSTRB 72    // bf16 elements

#define KSLOT 9216      // 32*72*4 bytes
#define VSLOT 36864     // 256*72*2 bytes
#define PSLOT 18432     // 128*72*2 bytes

#define OFF_QS 0                              // 128*36*4 = 18432
#define OFF_K  18432                          // 2*KSLOT  = 18432
#define OFF_V  36864                          // 2*VSLOT  = 73728
#define OFF_P  110592                         // 1*PSLOT  = 18432
#define OFF_L  129024                         // 2*128*4  = 1024
#define ATT_SMEM 130048

__global__ __launch_bounds__(512, 1) void attn_kernel(
    const float* __restrict__ qT, const float* __restrict__ k,
    const __nv_bfloat16* __restrict__ v, const float* __restrict__ query,
    const float* __restrict__ gamma, float* __restrict__ outp)
{
    extern __shared__ char smem[];
    uint32 sb = (uint32)__cvta_generic_to_shared(smem);
    float*         qs = (float*)(smem + OFF_QS);
    float*         ks = (float*)(smem + OFF_K);
    __nv_bfloat16* vs = (__nv_bfloat16*)(smem + OFF_V);
    __nv_bfloat16* ps = (__nv_bfloat16*)(smem + OFF_P);
    float*         lp = (float*)(smem + OFF_L);

    int tid  = threadIdx.x;
    int warp = tid >> 5;
    int lane = tid & 31;
    int lr = lane >> 2, lc = lane & 3;
    int b  = blockIdx.y;
    int i0 = blockIdx.x * BM;

    int srow  = (warp & 7) * 16;
    int chalf = warp >> 3;
    int scol  = chalf * 32;
    int pvrow = (warp & 3) * 32;
    int cb    = (warp >> 2) * 64;

    const float*         qTb = qT + ((size_t)b * NN + i0) * DQK;
    const float*         kb  = k  + (size_t)b * DQK * NN;
    const __nv_bfloat16* vb  = v  + (size_t)b * CQi * NN;

    auto prefetchKV = [&](int m0, int pb) {
        {
            int d = tid >> 4, ch = tid & 15;
            cp16p((char*)ks + pb * KSLOT + d * (KSTR * 4) + ch * 16,
                  kb + (size_t)d * NN + m0 + ch * 4);
        }
#pragma unroll
        for (int it = 0; it < 4; it++) {
            int idx = tid + it * 512;
            int c = idx >> 3, ch = idx & 7;
            cp16p((char*)vs + pb * VSLOT + c * (VSTRB * 2) + ch * 16,
                  vb + (size_t)c * NN + m0 + ch * 8);
        }
    };

#pragma unroll
    for (int it = 0; it < 2; it++) {
        int idx = tid + it * 512;
        int i = idx >> 3, ch = idx & 7;
        cp16p((char*)qs + i * (QSTR * 4) + ch * 16, qTb + i * DQK + ch * 4);
    }
    prefetchKV(0, 0);
    cp_commit();
    cp_wait0();
    __syncthreads();

    uint32 qa[4][4];
#pragma unroll
    for (int kk = 0; kk < 4; kk++) {
        const float* ar = qs + (srow + lr) * QSTR + kk * 8 + lc;
        qa[kk][0] = __float_as_uint(ar[0]);
        qa[kk][1] = __float_as_uint(ar[8 * QSTR]);
        qa[kk][2] = __float_as_uint(ar[4]);
        qa[kk][3] = __float_as_uint(ar[8 * QSTR + 4]);
    }

    uint32 pA = sb + OFF_P
              + 2u * ((uint32)(pvrow + (lane & 15)) * PSTRB + ((lane >> 1) & 8));
    uint32 pBrel = 2u * ((uint32)(cb + (lane & 7) + ((lane >> 1) & 8)) * VSTRB
                         + (lane & 8));

    float lsum0 = 0.f, lsum1 = 0.f;
    float acc[2][8][4];
#pragma unroll
    for (int mt = 0; mt < 2; mt++)
#pragma unroll
        for (int nt = 0; nt < 8; nt++)
#pragma unroll
            for (int i = 0; i < 4; i++) acc[mt][nt][i] = 0.f;

    const int NIT = NN / BN;   // 64

    for (int t = 0; t < NIT; t++) {
        int buf = t & 1;
        if (t + 1 < NIT) { prefetchKV((t + 1) * BN, buf ^ 1); cp_commit(); }

        float sc[4][4];
#pragma unroll
        for (int nt = 0; nt < 4; nt++)
#pragma unroll
            for (int i = 0; i < 4; i++) sc[nt][i] = 0.f;

        const float* ksB = (const float*)((char*)ks + buf * KSLOT);
#pragma unroll
        for (int kk = 0; kk < 4; kk++) {
            const float* br = ksB + (kk * 8 + lc) * KSTR + scol + lr;
#pragma unroll
            for (int nt = 0; nt < 4; nt++) {
                uint32 b0 = __float_as_uint(br[nt * 8]);
                uint32 b1 = __float_as_uint(br[4 * KSTR + nt * 8]);
                mma_tf32(sc[nt][0], sc[nt][1], sc[nt][2], sc[nt][3],
                         qa[kk][0], qa[kk][1], qa[kk][2], qa[kk][3], b0, b1);
            }
        }

#pragma unroll
        for (int nt = 0; nt < 4; nt++) {
            float p0 = __expf(sc[nt][0]);
            float p1 = __expf(sc[nt][1]);
            float p2 = __expf(sc[nt][2]);
            float p3 = __expf(sc[nt][3]);
            __nv_bfloat162 h0 = __floats2bfloat162_rn(p0, p1);
            __nv_bfloat162 h1 = __floats2bfloat162_rn(p2, p3);
            float2 r0f = __bfloat1622float2(h0);
            float2 r1f = __bfloat1622float2(h1);
            lsum0 += r0f.x + r0f.y;
            lsum1 += r1f.x + r1f.y;
            int col = scol + nt * 8 + 2 * lc;
            *(__nv_bfloat162*)&ps[(srow + lr) * PSTRB + col]     = h0;
            *(__nv_bfloat162*)&ps[(srow + lr + 8) * PSTRB + col] = h1;
        }
        __syncthreads();

        uint32 pB = sb + OFF_V + (uint32)buf * VSLOT + pBrel;
#pragma unroll
        for (int kk = 0; kk < 4; kk++) {
            uint32 a[2][4];
#pragma unroll
            for (int mt = 0; mt < 2; mt++)
                ldsm_x4(a[mt][0], a[mt][1], a[mt][2], a[mt][3],
                        pA + 2u * ((uint32)mt * 16 * PSTRB + (uint32)kk * 16));
#pragma unroll
            for (int ntp = 0; ntp < 4; ntp++) {
                uint32 b0, b1, b2, b3;
                ldsm_x4(b0, b1, b2, b3,
                        pB + 2u * ((uint32)ntp * 16 * VSTRB + (uint32)kk * 16));
#pragma unroll
                for (int mt = 0; mt < 2; mt++) {
                    mma_bf16(acc[mt][2 * ntp][0],     acc[mt][2 * ntp][1],
                             acc[mt][2 * ntp][2],     acc[mt][2 * ntp][3],
                             a[mt][0], a[mt][1], a[mt][2], a[mt][3], b0, b1);
                    mma_bf16(acc[mt][2 * ntp + 1][0], acc[mt][2 * ntp + 1][1],
                             acc[mt][2 * ntp + 1][2], acc[mt][2 * ntp + 1][3],
                             a[mt][0], a[mt][1], a[mt][2], a[mt][3], b2, b3);
                }
            }
        }
        cp_wait0();
        __syncthreads();
    }

    lsum0 += __shfl_xor_sync(0xffffffffu, lsum0, 1);
    lsum0 += __shfl_xor_sync(0xffffffffu, lsum0, 2);
    lsum1 += __shfl_xor_sync(0xffffffffu, lsum1, 1);
    lsum1 += __shfl_xor_sync(0xffffffffu, lsum1, 2);
    if (lc == 0) {
        lp[chalf * BM + srow + lr]     = lsum0;
        lp[chalf * BM + srow + lr + 8] = lsum1;
    }
    __syncthreads();

    float gm = gamma[0];
    const float* qry = query + (size_t)b * CQi * NN + i0;
    float*       ob  = outp  + (size_t)b * CQi * NN + i0;
#pragma unroll
    for (int mt = 0; mt < 2; mt++) {
        int r0 = pvrow + mt * 16 + lr;
        int r1 = r0 + 8;
        float f0 = gm / (lp[r0] + lp[BM + r0]);
        float f1 = gm / (lp[r1] + lp[BM + r1]);
#pragma unroll
        for (int nt = 0; nt < 8; nt++) {
            int c = cb + nt * 8 + 2 * lc;
            size_t o00 = (size_t)c * NN + r0;
            size_t o01 = (size_t)(c + 1) * NN + r0;
            size_t o10 = (size_t)c * NN + r1;
            size_t o11 = (size_t)(c + 1) * NN + r1;
            ob[o00] = f0 * acc[mt][nt][0] + qry[o00];
            ob[o01] = f0 * acc[mt][nt][1] + qry[o01];
            ob[o10] = f1 * acc[mt][nt][2] + qry[o10];
            ob[o11] = f1 * acc[mt][nt][3] + qry[o11];
        }
    }
}

// ---------------- host launcher -------------------------------------------
extern "C" void kernel_launch(void* const* d_in, const int* in_sizes, int n_in,
                              void* d_out, int out_size)
{
    const float* query     = (const float*)d_in[0];
    const float* key_value = (const float*)d_in[1];
    const float* Wq = (const float*)d_in[2];
    const float* bq = (const float*)d_in[3];
    const float* Wk = (const float*)d_in[4];
    const float* bk = (const float*)d_in[5];
    const float* Wv = (const float*)d_in[6];
    const float* bv = (const float*)d_in[7];
    const float* gamma = (const float*)d_in[8];
    float* out = (float*)d_out;

    void* p;
    cudaGetSymbolAddress(&p, g_lo); float*         lo   = (float*)p;
    cudaGetSymbolAddress(&p, g_q);  float*         qb   = (float*)p;
    cudaGetSymbolAddress(&p, g_k);  float*         kb   = (float*)p;
    cudaGetSymbolAddress(&p, g_v);  __nv_bfloat16* vbuf = (__nv_bfloat16*)p;

    float* k_low = lo;                             // [b][32][1024]
    float* v_low = lo + (size_t)BQ * DQK * NLOW;   // [b][256][1024]

    size_t smQ = (2 * 32 * 260 + 2 * 32 * 36) * sizeof(float);
    size_t smV = (2 * 32 * 132 + 2 * 128 * 36) * sizeof(float);
    cudaFuncSetAttribute(proj_mma<256, 32, 256, 16, 64, 1>,
                         cudaFuncAttributeMaxDynamicSharedMemorySize, (int)smQ);
    cudaFuncSetAttribute(proj_mma<512, 32, 256, 16, 64, 0>,
                         cudaFuncAttributeMaxDynamicSharedMemorySize, (int)smQ);
    cudaFuncSetAttribute(proj_mma<512, 128, 128, 32, 64, 0>,
                         cudaFuncAttributeMaxDynamicSharedMemorySize, (int)smV);

    // 1) projections at LOW resolution (project-then-resize; operators commute)
    proj_mma<512, 32, 256, 16, 64, 0><<<dim3(NLOW / 256, BQ, 1), 256, smQ>>>(
        key_value, Wk, bk, k_low, 32, NLOW);
    proj_mma<512, 128, 128, 32, 64, 0><<<dim3(NLOW / 128, BQ, 2), 256, smV>>>(
        key_value, Wv, bv, v_low, 256, NLOW);
    // Q projection at full resolution (input is already 64x64)
    proj_mma<256, 32, 256, 16, 64, 1><<<dim3(NN / 256, BQ, 1), 256, smQ>>>(
        query, Wq, bq, qb, 32, NN);

    // 2) upsample projected K (tf32 f32) and V (bf16)
    upsample_kernel<0><<<(BQ * DQK * NN + 255) / 256, 256>>>(
        k_low, kb, BQ * DQK * NN);
    upsample_kernel<1><<<(BQ * CQi * NN + 255) / 256, 256>>>(
        v_low, vbuf, BQ * CQi * NN);

    // 3) flash attention + residual
    cudaFuncSetAttribute(attn_kernel, cudaFuncAttributeMaxDynamicSharedMemorySize,
                         ATT_SMEM);
    attn_kernel<<<dim3(NN / BM, BQ), 512, ATT_SMEM>>>(qb, kb, vbuf, query,
                                                      gamma, out);
}

// round 15
// speedup vs baseline: 1.6129x; 1.1253x over previous
#include <cuda_runtime.h>
#include <cuda_bf16.h>
#include <cstdint>

// Problem constants
#define BQ   8
#define CQi  256
#define CKV  512
#define NN   4096
#define DQK  32
#define NLOW 1024    // 32x32 low-res spatial

typedef unsigned long long ull;
typedef unsigned int uint32;

// ---------------- scratch (static device globals; no allocations) ----------
__device__ float          g_lo[BQ * DQK * NLOW];   // lowres K (f32)
__device__ __nv_bfloat16  g_vl[BQ * CQi * NLOW];   // lowres V (bf16)
__device__ float          g_q [BQ * NN * DQK];     // Q^T [b][n][d] tf32
__device__ float          g_k [BQ * DQK * NN];     // K   [b][d][n] tf32

// ---------------- helpers ---------------------------------------------------
__device__ __forceinline__ float tf32r(float x) {
    uint32 u;
    asm("cvt.rna.tf32.f32 %0, %1;" : "=r"(u) : "f"(x));
    return __uint_as_float(u);
}
__device__ __forceinline__ void mma_tf32(
    float& c0, float& c1, float& c2, float& c3,
    uint32 a0, uint32 a1, uint32 a2, uint32 a3,
    uint32 b0, uint32 b1)
{
    asm volatile(
        "mma.sync.aligned.m16n8k8.row.col.f32.tf32.tf32.f32 "
        "{%0,%1,%2,%3}, {%4,%5,%6,%7}, {%8,%9}, {%0,%1,%2,%3};"
        : "+f"(c0), "+f"(c1), "+f"(c2), "+f"(c3)
        : "r"(a0), "r"(a1), "r"(a2), "r"(a3), "r"(b0), "r"(b1));
}
__device__ __forceinline__ void mma_bf16(
    float& c0, float& c1, float& c2, float& c3,
    uint32 a0, uint32 a1, uint32 a2, uint32 a3,
    uint32 b0, uint32 b1)
{
    asm volatile(
        "mma.sync.aligned.m16n8k16.row.col.f32.bf16.bf16.f32 "
        "{%0,%1,%2,%3}, {%4,%5,%6,%7}, {%8,%9}, {%0,%1,%2,%3};"
        : "+f"(c0), "+f"(c1), "+f"(c2), "+f"(c3)
        : "r"(a0), "r"(a1), "r"(a2), "r"(a3), "r"(b0), "r"(b1));
}
__device__ __forceinline__ void ldsm_x4(uint32& r0, uint32& r1, uint32& r2,
                                        uint32& r3, uint32 addr)
{
    asm volatile(
        "ldmatrix.sync.aligned.m8n8.x4.shared.b16 {%0,%1,%2,%3}, [%4];"
        : "=r"(r0), "=r"(r1), "=r"(r2), "=r"(r3) : "r"(addr));
}
__device__ __forceinline__ void cp16p(void* sdst, const void* gsrc) {
    uint32 s = (uint32)__cvta_generic_to_shared(sdst);
    asm volatile("cp.async.cg.shared.global [%0], [%1], 16;" :: "r"(s), "l"(gsrc));
}
__device__ __forceinline__ void cp_commit() {
    asm volatile("cp.async.commit_group;" ::: "memory");
}
__device__ __forceinline__ void cp_wait0() {
    asm volatile("cp.async.wait_group 0;" ::: "memory");
}

// ---------------- bilinear 2x upsample (half-pixel, clamped) ---------------
template <int OUTMODE>
__global__ void upsample_kernel(const float* __restrict__ src,
                                void* __restrict__ dst, int total)
{
    int idx = blockIdx.x * 256 + threadIdx.x;
    if (idx >= total) return;
    int x  = idx & 63;
    int y  = (idx >> 6) & 63;
    int cb = idx >> 12;
    float fx = 0.5f * (float)x - 0.25f;
    float fy = 0.5f * (float)y - 0.25f;
    float fx0 = floorf(fx), fy0 = floorf(fy);
    float wx = fx - fx0, wy = fy - fy0;
    int x0 = max((int)fx0, 0), x1 = min((int)fx0 + 1, 31);
    int y0 = max((int)fy0, 0), y1 = min((int)fy0 + 1, 31);
    const float* s = src + (size_t)cb * 1024;
    float v00 = s[y0 * 32 + x0], v01 = s[y0 * 32 + x1];
    float v10 = s[y1 * 32 + x0], v11 = s[y1 * 32 + x1];
    float top = v00 + wx * (v01 - v00);
    float bot = v10 + wx * (v11 - v10);
    float val = top + wy * (bot - top);
    if (OUTMODE == 0) ((float*)dst)[idx] = tf32r(val);
    else ((__nv_bfloat16*)dst)[idx] = __float2bfloat16(val);
}

// ---------------- tf32-mma 1x1 conv GEMM -----------------------------------
// OUTM: 0 = plain f32 [d][n], 1 = tf32 transposed [n][DQK], 3 = bf16 [d][n]
template <int CIN, int DT, int NT, int WM, int WN, int OUTM>
__global__ __launch_bounds__(256) void proj_mma(
    const float* __restrict__ in, const float* __restrict__ W,
    const float* __restrict__ bias, void* __restrict__ outp,
    int dout_total, int nspat)
{
    constexpr int BK  = 32;
    constexpr int NTP = NT + 4;
    constexpr int WSP = 36;
    constexpr int KCH = CIN / BK;
    constexpr int MT  = WM / 16;
    constexpr int NTl = WN / 8;
    constexpr int WARPS_N = NT / WN;

    extern __shared__ float smx[];
    float* ins = smx;
    float* Ws  = smx + 2 * BK * NTP;

    int tid  = threadIdx.x;
    int warp = tid >> 5, lane = tid & 31;
    int lr = lane >> 2, lc = lane & 3;
    int nwarp = warp % WARPS_N, mwarp = warp / WARPS_N;
    int mb = mwarp * WM, nb = nwarp * WN;

    int b  = blockIdx.y;
    int n0 = blockIdx.x * NT;
    int d0 = blockIdx.z * DT;

    const float* inb = in + (size_t)b * CIN * nspat + n0;

    float acc[MT][NTl][4];
#pragma unroll
    for (int mt = 0; mt < MT; mt++)
#pragma unroll
        for (int nt = 0; nt < NTl; nt++)
#pragma unroll
            for (int i = 0; i < 4; i++) acc[mt][nt][i] = 0.f;

    auto prefetch = [&](int kc, int pb) {
        float* insB = ins + pb * BK * NTP;
        float* WsB  = Ws  + pb * DT * WSP;
        constexpr int INIT = BK * NT / 4 / 256;
#pragma unroll
        for (int it = 0; it < INIT; it++) {
            int idx = tid + it * 256;
            int c = idx / (NT / 4), j4 = (idx % (NT / 4)) * 4;
            cp16p(insB + c * NTP + j4, inb + (size_t)(kc * BK + c) * nspat + j4);
        }
        constexpr int WIT = DT * 8 / 256;
#pragma unroll
        for (int it = 0; it < (WIT > 0 ? WIT : 1); it++) {
            int idx = tid + it * 256;
            if (idx < DT * 8) {
                int d = idx >> 3, cj = (idx & 7) * 4;
                cp16p(WsB + d * WSP + cj, W + (size_t)(d0 + d) * CIN + kc * BK + cj);
            }
        }
    };

    prefetch(0, 0);
    cp_commit();
    cp_wait0();
    __syncthreads();

    for (int kc = 0; kc < KCH; kc++) {
        int buf = kc & 1;
        if (kc + 1 < KCH) { prefetch(kc + 1, buf ^ 1); cp_commit(); }
        const float* insB = ins + buf * BK * NTP;
        const float* WsB  = Ws  + buf * DT * WSP;
#pragma unroll
        for (int kk = 0; kk < 4; kk++) {
            uint32 a[MT][4];
#pragma unroll
            for (int mt = 0; mt < MT; mt++) {
                const float* ar = WsB + (mb + mt * 16 + lr) * WSP + kk * 8 + lc;
                a[mt][0] = __float_as_uint(ar[0]);
                a[mt][1] = __float_as_uint(ar[8 * WSP]);
                a[mt][2] = __float_as_uint(ar[4]);
                a[mt][3] = __float_as_uint(ar[8 * WSP + 4]);
            }
            const float* br = insB + (kk * 8 + lc) * NTP + nb + lr;
#pragma unroll
            for (int nt = 0; nt < NTl; nt++) {
                uint32 b0 = __float_as_uint(br[nt * 8]);
                uint32 b1 = __float_as_uint(br[4 * NTP + nt * 8]);
#pragma unroll
                for (int mt = 0; mt < MT; mt++)
                    mma_tf32(acc[mt][nt][0], acc[mt][nt][1],
                             acc[mt][nt][2], acc[mt][nt][3],
                             a[mt][0], a[mt][1], a[mt][2], a[mt][3], b0, b1);
            }
        }
        cp_wait0();
        __syncthreads();
    }

#pragma unroll
    for (int mt = 0; mt < MT; mt++) {
        int dA = d0 + mb + mt * 16 + lr;
        float bA = bias[dA], bB = bias[dA + 8];
        if (OUTM == 1) {
            float* op = (float*)outp;
#pragma unroll
            for (int nt = 0; nt < NTl; nt++) {
                int nc = n0 + nb + nt * 8 + 2 * lc;
                float* o = op + ((size_t)b * nspat + nc) * DQK;
                o[dA]           = tf32r(acc[mt][nt][0] + bA);
                o[DQK + dA]     = tf32r(acc[mt][nt][1] + bA);
                o[dA + 8]       = tf32r(acc[mt][nt][2] + bB);
                o[DQK + dA + 8] = tf32r(acc[mt][nt][3] + bB);
            }
        } else if (OUTM == 0) {
            float* oA = (float*)outp + ((size_t)b * dout_total + dA) * nspat + n0 + nb;
            float* oB = oA + (size_t)8 * nspat;
#pragma unroll
            for (int nt = 0; nt < NTl; nt++) {
                int col = nt * 8 + 2 * lc;
                *(float2*)&oA[col] = make_float2(acc[mt][nt][0] + bA,
                                                acc[mt][nt][1] + bA);
                *(float2*)&oB[col] = make_float2(acc[mt][nt][2] + bB,
                                                acc[mt][nt][3] + bB);
            }
        } else {
            __nv_bfloat16* oA = (__nv_bfloat16*)outp
                + ((size_t)b * dout_total + dA) * nspat + n0 + nb;
            __nv_bfloat16* oB = oA + (size_t)8 * nspat;
#pragma unroll
            for (int nt = 0; nt < NTl; nt++) {
                int col = nt * 8 + 2 * lc;
                *(__nv_bfloat162*)&oA[col] =
                    __floats2bfloat162_rn(acc[mt][nt][0] + bA, acc[mt][nt][1] + bA);
                *(__nv_bfloat162*)&oB[col] =
                    __floats2bfloat162_rn(acc[mt][nt][2] + bB, acc[mt][nt][3] + bB);
            }
        }
    }
}

// ---------------- flash attention with folded low-res PV -------------------
// BM=128 rows/CTA (tile = one image row y, x 0..63), 512 threads.
// S + softmax identical to R13 (P kept fp32). P folded through the bilinear
// operator into PL[2][128][32] (fp32, thread-exclusive). Every 2 tiles a
// low-res row completes -> bf16 conversion -> 32-k GEMM vs Vlow row.
#define BM 128
#define BN 64
#define QSTR 36     // f32
#define KSTR 72     // f32
#define PHSTR 68    // f32 (64 + 4 pad)
#define PLSTR 33    // f32
#define PLBSTR 40   // bf16 (32 + 8 pad; 80B rows, ldsm-aligned)
#define VLSTR 40    // bf16

#define KSLOT  9216                 // 32*72*4
#define PLSLOT (128 * PLSTR * 4)    // 16896
#define VLSLOT (256 * VLSTR * 2)    // 20480

#define OFF_QS  0                   // 18432
#define OFF_K   18432               // 2*9216  -> 36864
#define OFF_PH  36864               // 34816   -> 71680
#define OFF_PL  71680               // 2*16896 -> 105472
#define OFF_PLB 105472              // 10240   -> 115712
#define OFF_VL  115712              // 2*20480 -> 156672
#define OFF_L   156672              // 1024    -> 157696
#define ATT_SMEM 157696

__global__ __launch_bounds__(512, 1) void attn_kernel(
    const float* __restrict__ qT, const float* __restrict__ k,
    const __nv_bfloat16* __restrict__ vl, const float* __restrict__ query,
    const float* __restrict__ gamma, float* __restrict__ outp)
{
    extern __shared__ char smem[];
    uint32 sb = (uint32)__cvta_generic_to_shared(smem);
    float*         qs  = (float*)(smem + OFF_QS);
    float*         ks  = (float*)(smem + OFF_K);
    float*         ph  = (float*)(smem + OFF_PH);
    float*         plf = (float*)(smem + OFF_PL);
    __nv_bfloat16* plb = (__nv_bfloat16*)(smem + OFF_PLB);
    __nv_bfloat16* vls = (__nv_bfloat16*)(smem + OFF_VL);
    float*         lp  = (float*)(smem + OFF_L);

    int tid  = threadIdx.x;
    int warp = tid >> 5;
    int lane = tid & 31;
    int lr = lane >> 2, lc = lane & 3;
    int b  = blockIdx.y;
    int i0 = blockIdx.x * BM;

    int srow  = (warp & 7) * 16;
    int chalf = warp >> 3;
    int scol  = chalf * 32;
    int pvrow = (warp & 3) * 32;
    int cb    = (warp >> 2) * 64;

    // fold ownership: thread -> (n_f, j in jg*8..jg*8+7)
    int n_f = tid >> 2;
    int jg  = tid & 3;

    const float*         qTb = qT + ((size_t)b * NN + i0) * DQK;
    const float*         kb  = k  + (size_t)b * DQK * NN;
    const __nv_bfloat16* vlb = vl + (size_t)b * CQi * NLOW;

    auto prefetchK = [&](int m0, int pb) {
        int d = tid >> 4, ch = tid & 15;
        cp16p((char*)ks + pb * KSLOT + d * (KSTR * 4) + ch * 16,
              kb + (size_t)d * NN + m0 + ch * 4);
    };
    auto prefetchVL = [&](int r, int slot) {
        // Vlow row r: [256 c][32 j] bf16, 1024 16B chunks
#pragma unroll
        for (int it = 0; it < 2; it++) {
            int idx = tid + it * 512;
            int c = idx >> 2, ch = idx & 3;
            cp16p((char*)vls + slot * VLSLOT + c * (VLSTR * 2) + ch * 16,
                  vlb + (size_t)c * NLOW + r * 32 + ch * 8);
        }
    };

    // ---- prolog: zero PL, load Q + K(0) ----
    for (int i = tid; i < 2 * 128 * PLSTR; i += 512) plf[i] = 0.f;
#pragma unroll
    for (int it = 0; it < 2; it++) {
        int idx = tid + it * 512;
        int i = idx >> 3, ch = idx & 7;
        cp16p((char*)qs + i * (QSTR * 4) + ch * 16, qTb + i * DQK + ch * 4);
    }
    prefetchK(0, 0);
    cp_commit();
    cp_wait0();
    __syncthreads();

    // ---- hoist Q fragments ----
    uint32 qa[4][4];
#pragma unroll
    for (int kk = 0; kk < 4; kk++) {
        const float* ar = qs + (srow + lr) * QSTR + kk * 8 + lc;
        qa[kk][0] = __float_as_uint(ar[0]);
        qa[kk][1] = __float_as_uint(ar[8 * QSTR]);
        qa[kk][2] = __float_as_uint(ar[4]);
        qa[kk][3] = __float_as_uint(ar[8 * QSTR + 4]);
    }

    // ldsm invariants
    uint32 pA_base = sb + OFF_PLB
        + 2u * ((uint32)(pvrow + (lane & 15)) * PLBSTR + ((lane >> 1) & 8));
    uint32 pB_rel = 2u * ((uint32)(cb + (lane & 7) + ((lane >> 1) & 8)) * VLSTR
                          + (lane & 8));

    float lsum0 = 0.f, lsum1 = 0.f;
    float acc[2][8][4];
#pragma unroll
    for (int mt = 0; mt < 2; mt++)
#pragma unroll
        for (int nt = 0; nt < 8; nt++)
#pragma unroll
            for (int i = 0; i < 4; i++) acc[mt][nt][i] = 0.f;

    for (int y = 0; y < 64; y++) {
        int buf = y & 1;
        if (y + 1 < 64) prefetchK((y + 1) * BN, buf ^ 1);
        if ((y & 1) == 0) prefetchVL(y >> 1, (y >> 1) & 1);
        cp_commit();

        // ---- S = Q K^T (tf32) ----
        float sc[4][4];
#pragma unroll
        for (int nt = 0; nt < 4; nt++)
#pragma unroll
            for (int i = 0; i < 4; i++) sc[nt][i] = 0.f;
        const float* ksB = (const float*)((char*)ks + buf * KSLOT);
#pragma unroll
        for (int kk = 0; kk < 4; kk++) {
            const float* br = ksB + (kk * 8 + lc) * KSTR + scol + lr;
#pragma unroll
            for (int nt = 0; nt < 4; nt++) {
                uint32 b0 = __float_as_uint(br[nt * 8]);
                uint32 b1 = __float_as_uint(br[4 * KSTR + nt * 8]);
                mma_tf32(sc[nt][0], sc[nt][1], sc[nt][2], sc[nt][3],
                         qa[kk][0], qa[kk][1], qa[kk][2], qa[kk][3], b0, b1);
            }
        }

        // ---- softmax (fp32 p), store PH, sum l ----
#pragma unroll
        for (int nt = 0; nt < 4; nt++) {
            float p0 = __expf(sc[nt][0]);
            float p1 = __expf(sc[nt][1]);
            float p2 = __expf(sc[nt][2]);
            float p3 = __expf(sc[nt][3]);
            lsum0 += p0 + p1;
            lsum1 += p2 + p3;
            int col = scol + nt * 8 + 2 * lc;
            *(float2*)&ph[(srow + lr) * PHSTR + col]     = make_float2(p0, p1);
            *(float2*)&ph[(srow + lr + 8) * PHSTR + col] = make_float2(p2, p3);
        }
        __syncthreads();   // PH complete

        // ---- fold PH row y into PL (x 4-tap then y weights) ----
        {
            int r0, r1; float w0, w1;
            if (y & 1) { int t = y >> 1; r0 = t; w0 = 0.75f;
                         r1 = (t + 1 < 32) ? t + 1 : 31; w1 = 0.25f; }
            else       { int t = y >> 1; r0 = (t - 1 >= 0) ? t - 1 : 0; w0 = 0.25f;
                         r1 = t; w1 = 0.75f; }
            bool merged = (r0 == r1);
            float* pl0 = plf + (r0 & 1) * (128 * PLSTR);
            float* pl1 = plf + (r1 & 1) * (128 * PLSTR);
            const float* Pn = ph + n_f * PHSTR;
#pragma unroll
            for (int i = 0; i < 8; i++) {
                int j = jg * 8 + i;
                int xm1 = (2 * j - 1 >= 0) ? 2 * j - 1 : 0;
                int xp2 = (2 * j + 2 <= 63) ? 2 * j + 2 : 63;
                float xs = 0.75f * (Pn[2 * j] + Pn[2 * j + 1])
                         + 0.25f * (Pn[xm1] + Pn[xp2]);
                int idx = n_f * PLSTR + j;
                if (merged) pl0[idx] += xs;
                else { pl0[idx] += w0 * xs; pl1[idx] += w1 * xs; }
            }
        }

        // ---- completion: convert PL -> bf16, zero, GEMM vs Vlow row ----
        bool complete = (((y & 1) == 0 && y >= 2) || y == 63);
        if (complete) {
            int rc = (y == 63) ? 31 : ((y - 2) >> 1);
            float* plc = plf + (rc & 1) * (128 * PLSTR);
#pragma unroll
            for (int i = 0; i < 8; i++) {
                int j = jg * 8 + i;
                int idx = n_f * PLSTR + j;
                plb[n_f * PLBSTR + j] = __float2bfloat16(plc[idx]);
                plc[idx] = 0.f;
            }
            __syncthreads();   // PLb ready (Vlow row rc arrived last iter)

            uint32 pB = sb + OFF_VL + (uint32)(rc & 1) * VLSLOT + pB_rel;
#pragma unroll
            for (int kk = 0; kk < 2; kk++) {
                uint32 a[2][4];
#pragma unroll
                for (int mt = 0; mt < 2; mt++)
                    ldsm_x4(a[mt][0], a[mt][1], a[mt][2], a[mt][3],
                            pA_base + 2u * ((uint32)mt * 16 * PLBSTR
                                            + (uint32)kk * 16));
#pragma unroll
                for (int ntp = 0; ntp < 4; ntp++) {
                    uint32 b0, b1, b2, b3;
                    ldsm_x4(b0, b1, b2, b3,
                            pB + 2u * ((uint32)ntp * 16 * VLSTR
                                       + (uint32)kk * 16));
#pragma unroll
                    for (int mt = 0; mt < 2; mt++) {
                        mma_bf16(acc[mt][2 * ntp][0],     acc[mt][2 * ntp][1],
                                 acc[mt][2 * ntp][2],     acc[mt][2 * ntp][3],
                                 a[mt][0], a[mt][1], a[mt][2], a[mt][3], b0, b1);
                        mma_bf16(acc[mt][2 * ntp + 1][0], acc[mt][2 * ntp + 1][1],
                                 acc[mt][2 * ntp + 1][2], acc[mt][2 * ntp + 1][3],
                                 a[mt][0], a[mt][1], a[mt][2], a[mt][3], b2, b3);
                    }
                }
            }
        }
        cp_wait0();
        __syncthreads();   // K(y+1)/Vlow arrived; PH free; folds visible
    }

    // ---- half-row-sum reduction ----
    lsum0 += __shfl_xor_sync(0xffffffffu, lsum0, 1);
    lsum0 += __shfl_xor_sync(0xffffffffu, lsum0, 2);
    lsum1 += __shfl_xor_sync(0xffffffffu, lsum1, 1);
    lsum1 += __shfl_xor_sync(0xffffffffu, lsum1, 2);
    if (lc == 0) {
        lp[chalf * BM + srow + lr]     = lsum0;
        lp[chalf * BM + srow + lr + 8] = lsum1;
    }
    __syncthreads();

    // ---- epilogue: out = gamma * acc / l + query ----
    float gm = gamma[0];
    const float* qry = query + (size_t)b * CQi * NN + i0;
    float*       ob  = outp  + (size_t)b * CQi * NN + i0;
#pragma unroll
    for (int mt = 0; mt < 2; mt++) {
        int r0 = pvrow + mt * 16 + lr;
        int r1 = r0 + 8;
        float f0 = gm / (lp[r0] + lp[BM + r0]);
        float f1 = gm / (lp[r1] + lp[BM + r1]);
#pragma unroll
        for (int nt = 0; nt < 8; nt++) {
            int c = cb + nt * 8 + 2 * lc;
            size_t o00 = (size_t)c * NN + r0;
            size_t o01 = (size_t)(c + 1) * NN + r0;
            size_t o10 = (size_t)c * NN + r1;
            size_t o11 = (size_t)(c + 1) * NN + r1;
            ob[o00] = f0 * acc[mt][nt][0] + qry[o00];
            ob[o01] = f0 * acc[mt][nt][1] + qry[o01];
            ob[o10] = f1 * acc[mt][nt][2] + qry[o10];
            ob[o11] = f1 * acc[mt][nt][3] + qry[o11];
        }
    }
}

// ---------------- host launcher -------------------------------------------
extern "C" void kernel_launch(void* const* d_in, const int* in_sizes, int n_in,
                              void* d_out, int out_size)
{
    const float* query     = (const float*)d_in[0];
    const float* key_value = (const float*)d_in[1];
    const float* Wq = (const float*)d_in[2];
    const float* bq = (const float*)d_in[3];
    const float* Wk = (const float*)d_in[4];
    const float* bk = (const float*)d_in[5];
    const float* Wv = (const float*)d_in[6];
    const float* bv = (const float*)d_in[7];
    const float* gamma = (const float*)d_in[8];
    float* out = (float*)d_out;

    void* p;
    cudaGetSymbolAddress(&p, g_lo); float*         k_low = (float*)p;
    cudaGetSymbolAddress(&p, g_vl); __nv_bfloat16* v_low = (__nv_bfloat16*)p;
    cudaGetSymbolAddress(&p, g_q);  float*         qb    = (float*)p;
    cudaGetSymbolAddress(&p, g_k);  float*         kb    = (float*)p;

    size_t smQ = (2 * 32 * 260 + 2 * 32 * 36) * sizeof(float);
    size_t smV = (2 * 32 * 132 + 2 * 128 * 36) * sizeof(float);
    cudaFuncSetAttribute(proj_mma<256, 32, 256, 16, 64, 1>,
                         cudaFuncAttributeMaxDynamicSharedMemorySize, (int)smQ);
    cudaFuncSetAttribute(proj_mma<512, 32, 256, 16, 64, 0>,
                         cudaFuncAttributeMaxDynamicSharedMemorySize, (int)smQ);
    cudaFuncSetAttribute(proj_mma<512, 128, 128, 32, 64, 3>,
                         cudaFuncAttributeMaxDynamicSharedMemorySize, (int)smV);

    // 1) low-res projections (project-then-resize commutes)
    proj_mma<512, 32, 256, 16, 64, 0><<<dim3(NLOW / 256, BQ, 1), 256, smQ>>>(
        key_value, Wk, bk, k_low, 32, NLOW);
    proj_mma<512, 128, 128, 32, 64, 3><<<dim3(NLOW / 128, BQ, 2), 256, smV>>>(
        key_value, Wv, bv, v_low, 256, NLOW);
    // Q at full resolution
    proj_mma<256, 32, 256, 16, 64, 1><<<dim3(NN / 256, BQ, 1), 256, smQ>>>(
        query, Wq, bq, qb, 32, NN);

    // 2) upsample K only (V stays at low res; PV is folded in-kernel)
    upsample_kernel<0><<<(BQ * DQK * NN + 255) / 256, 256>>>(
        k_low, kb, BQ * DQK * NN);

    // 3) flash attention with folded PV + residual
    cudaFuncSetAttribute(attn_kernel, cudaFuncAttributeMaxDynamicSharedMemorySize,
                         ATT_SMEM);
    attn_kernel<<<dim3(NN / BM, BQ), 512, ATT_SMEM>>>(qb, kb, v_low, query,
                                                      gamma, out);
}

// round 16
// speedup vs baseline: 1.6946x; 1.0506x over previous
#include <cuda_runtime.h>
#include <cuda_bf16.h>
#include <cstdint>

// Problem constants
#define BQ   8
#define CQi  256
#define CKV  512
#define NN   4096
#define DQK  32
#define NLOW 1024    // 32x32 low-res spatial

typedef unsigned long long ull;
typedef unsigned int uint32;

// ---------------- scratch (static device globals; no allocations) ----------
__device__ float          g_lo[BQ * DQK * NLOW];   // lowres K (f32)
__device__ __nv_bfloat16  g_vl[BQ * CQi * NLOW];   // lowres V (bf16)
__device__ float          g_q [BQ * NN * DQK];     // Q^T [b][n][d] tf32
__device__ float          g_k [BQ * DQK * NN];     // K   [b][d][n] tf32

// ---------------- helpers ---------------------------------------------------
__device__ __forceinline__ float tf32r(float x) {
    uint32 u;
    asm("cvt.rna.tf32.f32 %0, %1;" : "=r"(u) : "f"(x));
    return __uint_as_float(u);
}
__device__ __forceinline__ void mma_tf32(
    float& c0, float& c1, float& c2, float& c3,
    uint32 a0, uint32 a1, uint32 a2, uint32 a3,
    uint32 b0, uint32 b1)
{
    asm volatile(
        "mma.sync.aligned.m16n8k8.row.col.f32.tf32.tf32.f32 "
        "{%0,%1,%2,%3}, {%4,%5,%6,%7}, {%8,%9}, {%0,%1,%2,%3};"
        : "+f"(c0), "+f"(c1), "+f"(c2), "+f"(c3)
        : "r"(a0), "r"(a1), "r"(a2), "r"(a3), "r"(b0), "r"(b1));
}
__device__ __forceinline__ void mma_bf16(
    float& c0, float& c1, float& c2, float& c3,
    uint32 a0, uint32 a1, uint32 a2, uint32 a3,
    uint32 b0, uint32 b1)
{
    asm volatile(
        "mma.sync.aligned.m16n8k16.row.col.f32.bf16.bf16.f32 "
        "{%0,%1,%2,%3}, {%4,%5,%6,%7}, {%8,%9}, {%0,%1,%2,%3};"
        : "+f"(c0), "+f"(c1), "+f"(c2), "+f"(c3)
        : "r"(a0), "r"(a1), "r"(a2), "r"(a3), "r"(b0), "r"(b1));
}
__device__ __forceinline__ void ldsm_x4(uint32& r0, uint32& r1, uint32& r2,
                                        uint32& r3, uint32 addr)
{
    asm volatile(
        "ldmatrix.sync.aligned.m8n8.x4.shared.b16 {%0,%1,%2,%3}, [%4];"
        : "=r"(r0), "=r"(r1), "=r"(r2), "=r"(r3) : "r"(addr));
}
__device__ __forceinline__ void cp16p(void* sdst, const void* gsrc) {
    uint32 s = (uint32)__cvta_generic_to_shared(sdst);
    asm volatile("cp.async.cg.shared.global [%0], [%1], 16;" :: "r"(s), "l"(gsrc));
}
__device__ __forceinline__ void cp_commit() {
    asm volatile("cp.async.commit_group;" ::: "memory");
}
__device__ __forceinline__ void cp_wait0() {
    asm volatile("cp.async.wait_group 0;" ::: "memory");
}

// ---------------- bilinear 2x upsample (half-pixel, clamped) ---------------
template <int OUTMODE>
__global__ void upsample_kernel(const float* __restrict__ src,
                                void* __restrict__ dst, int total)
{
    int idx = blockIdx.x * 256 + threadIdx.x;
    if (idx >= total) return;
    int x  = idx & 63;
    int y  = (idx >> 6) & 63;
    int cb = idx >> 12;
    float fx = 0.5f * (float)x - 0.25f;
    float fy = 0.5f * (float)y - 0.25f;
    float fx0 = floorf(fx), fy0 = floorf(fy);
    float wx = fx - fx0, wy = fy - fy0;
    int x0 = max((int)fx0, 0), x1 = min((int)fx0 + 1, 31);
    int y0 = max((int)fy0, 0), y1 = min((int)fy0 + 1, 31);
    const float* s = src + (size_t)cb * 1024;
    float v00 = s[y0 * 32 + x0], v01 = s[y0 * 32 + x1];
    float v10 = s[y1 * 32 + x0], v11 = s[y1 * 32 + x1];
    float top = v00 + wx * (v01 - v00);
    float bot = v10 + wx * (v11 - v10);
    float val = top + wy * (bot - top);
    if (OUTMODE == 0) ((float*)dst)[idx] = tf32r(val);
    else ((__nv_bfloat16*)dst)[idx] = __float2bfloat16(val);
}

// ---------------- tf32-mma 1x1 conv GEMM -----------------------------------
// OUTM: 0 = plain f32 [d][n], 1 = tf32 transposed [n][DQK], 3 = bf16 [d][n]
template <int CIN, int DT, int NT, int WM, int WN, int OUTM>
__global__ __launch_bounds__(256) void proj_mma(
    const float* __restrict__ in, const float* __restrict__ W,
    const float* __restrict__ bias, void* __restrict__ outp,
    int dout_total, int nspat)
{
    constexpr int BK  = 32;
    constexpr int NTP = NT + 4;
    constexpr int WSP = 36;
    constexpr int KCH = CIN / BK;
    constexpr int MT  = WM / 16;
    constexpr int NTl = WN / 8;
    constexpr int WARPS_N = NT / WN;

    extern __shared__ float smx[];
    float* ins = smx;
    float* Ws  = smx + 2 * BK * NTP;

    int tid  = threadIdx.x;
    int warp = tid >> 5, lane = tid & 31;
    int lr = lane >> 2, lc = lane & 3;
    int nwarp = warp % WARPS_N, mwarp = warp / WARPS_N;
    int mb = mwarp * WM, nb = nwarp * WN;

    int b  = blockIdx.y;
    int n0 = blockIdx.x * NT;
    int d0 = blockIdx.z * DT;

    const float* inb = in + (size_t)b * CIN * nspat + n0;

    float acc[MT][NTl][4];
#pragma unroll
    for (int mt = 0; mt < MT; mt++)
#pragma unroll
        for (int nt = 0; nt < NTl; nt++)
#pragma unroll
            for (int i = 0; i < 4; i++) acc[mt][nt][i] = 0.f;

    auto prefetch = [&](int kc, int pb) {
        float* insB = ins + pb * BK * NTP;
        float* WsB  = Ws  + pb * DT * WSP;
        constexpr int INIT = BK * NT / 4 / 256;
#pragma unroll
        for (int it = 0; it < INIT; it++) {
            int idx = tid + it * 256;
            int c = idx / (NT / 4), j4 = (idx % (NT / 4)) * 4;
            cp16p(insB + c * NTP + j4, inb + (size_t)(kc * BK + c) * nspat + j4);
        }
        constexpr int WIT = DT * 8 / 256;
#pragma unroll
        for (int it = 0; it < (WIT > 0 ? WIT : 1); it++) {
            int idx = tid + it * 256;
            if (idx < DT * 8) {
                int d = idx >> 3, cj = (idx & 7) * 4;
                cp16p(WsB + d * WSP + cj, W + (size_t)(d0 + d) * CIN + kc * BK + cj);
            }
        }
    };

    prefetch(0, 0);
    cp_commit();
    cp_wait0();
    __syncthreads();

    for (int kc = 0; kc < KCH; kc++) {
        int buf = kc & 1;
        if (kc + 1 < KCH) { prefetch(kc + 1, buf ^ 1); cp_commit(); }
        const float* insB = ins + buf * BK * NTP;
        const float* WsB  = Ws  + buf * DT * WSP;
#pragma unroll
        for (int kk = 0; kk < 4; kk++) {
            uint32 a[MT][4];
#pragma unroll
            for (int mt = 0; mt < MT; mt++) {
                const float* ar = WsB + (mb + mt * 16 + lr) * WSP + kk * 8 + lc;
                a[mt][0] = __float_as_uint(ar[0]);
                a[mt][1] = __float_as_uint(ar[8 * WSP]);
                a[mt][2] = __float_as_uint(ar[4]);
                a[mt][3] = __float_as_uint(ar[8 * WSP + 4]);
            }
            const float* br = insB + (kk * 8 + lc) * NTP + nb + lr;
#pragma unroll
            for (int nt = 0; nt < NTl; nt++) {
                uint32 b0 = __float_as_uint(br[nt * 8]);
                uint32 b1 = __float_as_uint(br[4 * NTP + nt * 8]);
#pragma unroll
                for (int mt = 0; mt < MT; mt++)
                    mma_tf32(acc[mt][nt][0], acc[mt][nt][1],
                             acc[mt][nt][2], acc[mt][nt][3],
                             a[mt][0], a[mt][1], a[mt][2], a[mt][3], b0, b1);
            }
        }
        cp_wait0();
        __syncthreads();
    }

#pragma unroll
    for (int mt = 0; mt < MT; mt++) {
        int dA = d0 + mb + mt * 16 + lr;
        float bA = bias[dA], bB = bias[dA + 8];
        if (OUTM == 1) {
            float* op = (float*)outp;
#pragma unroll
            for (int nt = 0; nt < NTl; nt++) {
                int nc = n0 + nb + nt * 8 + 2 * lc;
                float* o = op + ((size_t)b * nspat + nc) * DQK;
                o[dA]           = tf32r(acc[mt][nt][0] + bA);
                o[DQK + dA]     = tf32r(acc[mt][nt][1] + bA);
                o[dA + 8]       = tf32r(acc[mt][nt][2] + bB);
                o[DQK + dA + 8] = tf32r(acc[mt][nt][3] + bB);
            }
        } else if (OUTM == 0) {
            float* oA = (float*)outp + ((size_t)b * dout_total + dA) * nspat + n0 + nb;
            float* oB = oA + (size_t)8 * nspat;
#pragma unroll
            for (int nt = 0; nt < NTl; nt++) {
                int col = nt * 8 + 2 * lc;
                *(float2*)&oA[col] = make_float2(acc[mt][nt][0] + bA,
                                                acc[mt][nt][1] + bA);
                *(float2*)&oB[col] = make_float2(acc[mt][nt][2] + bB,
                                                acc[mt][nt][3] + bB);
            }
        } else {
            __nv_bfloat16* oA = (__nv_bfloat16*)outp
                + ((size_t)b * dout_total + dA) * nspat + n0 + nb;
            __nv_bfloat16* oB = oA + (size_t)8 * nspat;
#pragma unroll
            for (int nt = 0; nt < NTl; nt++) {
                int col = nt * 8 + 2 * lc;
                *(__nv_bfloat162*)&oA[col] =
                    __floats2bfloat162_rn(acc[mt][nt][0] + bA, acc[mt][nt][1] + bA);
                *(__nv_bfloat162*)&oB[col] =
                    __floats2bfloat162_rn(acc[mt][nt][2] + bB, acc[mt][nt][3] + bB);
            }
        }
    }
}

// ---------------- flash attention with folded low-res PV -------------------
// Identical to R15 except the fold / conversion are fully vectorized
// (float4 gather of PH, float4 RMW of PL, 16B PLB stores); PLSTR 33 -> 36.
#define BM 128
#define BN 64
#define QSTR 36     // f32
#define KSTR 72     // f32
#define PHSTR 68    // f32 (64 + 4 pad)
#define PLSTR 36    // f32 (32 + 4 pad, 16B-aligned rows)
#define PLBSTR 40   // bf16 (32 + 8 pad)
#define VLSTR 40    // bf16

#define KSLOT  9216                 // 32*72*4
#define PLSLOT (128 * PLSTR * 4)    // 18432
#define VLSLOT (256 * VLSTR * 2)    // 20480

#define OFF_QS  0                   // 18432
#define OFF_K   18432               // 18432  -> 36864
#define OFF_PH  36864               // 34816  -> 71680
#define OFF_PL  71680               // 36864  -> 108544
#define OFF_PLB 108544              // 10240  -> 118784
#define OFF_VL  118784              // 40960  -> 159744
#define OFF_L   159744              // 1024   -> 160768
#define ATT_SMEM 160768

__global__ __launch_bounds__(512, 1) void attn_kernel(
    const float* __restrict__ qT, const float* __restrict__ k,
    const __nv_bfloat16* __restrict__ vl, const float* __restrict__ query,
    const float* __restrict__ gamma, float* __restrict__ outp)
{
    extern __shared__ char smem[];
    uint32 sb = (uint32)__cvta_generic_to_shared(smem);
    float*         qs  = (float*)(smem + OFF_QS);
    float*         ks  = (float*)(smem + OFF_K);
    float*         ph  = (float*)(smem + OFF_PH);
    float*         plf = (float*)(smem + OFF_PL);
    __nv_bfloat16* plb = (__nv_bfloat16*)(smem + OFF_PLB);
    __nv_bfloat16* vls = (__nv_bfloat16*)(smem + OFF_VL);
    float*         lp  = (float*)(smem + OFF_L);

    int tid  = threadIdx.x;
    int warp = tid >> 5;
    int lane = tid & 31;
    int lr = lane >> 2, lc = lane & 3;
    int b  = blockIdx.y;
    int i0 = blockIdx.x * BM;

    int srow  = (warp & 7) * 16;
    int chalf = warp >> 3;
    int scol  = chalf * 32;
    int pvrow = (warp & 3) * 32;
    int cb    = (warp >> 2) * 64;

    int n_f = tid >> 2;
    int jg  = tid & 3;

    const float*         qTb = qT + ((size_t)b * NN + i0) * DQK;
    const float*         kb  = k  + (size_t)b * DQK * NN;
    const __nv_bfloat16* vlb = vl + (size_t)b * CQi * NLOW;

    auto prefetchK = [&](int m0, int pb) {
        int d = tid >> 4, ch = tid & 15;
        cp16p((char*)ks + pb * KSLOT + d * (KSTR * 4) + ch * 16,
              kb + (size_t)d * NN + m0 + ch * 4);
    };
    auto prefetchVL = [&](int r, int slot) {
#pragma unroll
        for (int it = 0; it < 2; it++) {
            int idx = tid + it * 512;
            int c = idx >> 2, ch = idx & 3;
            cp16p((char*)vls + slot * VLSLOT + c * (VLSTR * 2) + ch * 16,
                  vlb + (size_t)c * NLOW + r * 32 + ch * 8);
        }
    };

    // ---- prolog: zero PL, load Q + K(0) ----
    for (int i = tid; i < 2 * 128 * PLSTR; i += 512) plf[i] = 0.f;
#pragma unroll
    for (int it = 0; it < 2; it++) {
        int idx = tid + it * 512;
        int i = idx >> 3, ch = idx & 7;
        cp16p((char*)qs + i * (QSTR * 4) + ch * 16, qTb + i * DQK + ch * 4);
    }
    prefetchK(0, 0);
    cp_commit();
    cp_wait0();
    __syncthreads();

    // ---- hoist Q fragments ----
    uint32 qa[4][4];
#pragma unroll
    for (int kk = 0; kk < 4; kk++) {
        const float* ar = qs + (srow + lr) * QSTR + kk * 8 + lc;
        qa[kk][0] = __float_as_uint(ar[0]);
        qa[kk][1] = __float_as_uint(ar[8 * QSTR]);
        qa[kk][2] = __float_as_uint(ar[4]);
        qa[kk][3] = __float_as_uint(ar[8 * QSTR + 4]);
    }

    uint32 pA_base = sb + OFF_PLB
        + 2u * ((uint32)(pvrow + (lane & 15)) * PLBSTR + ((lane >> 1) & 8));
    uint32 pB_rel = 2u * ((uint32)(cb + (lane & 7) + ((lane >> 1) & 8)) * VLSTR
                          + (lane & 8));

    float lsum0 = 0.f, lsum1 = 0.f;
    float acc[2][8][4];
#pragma unroll
    for (int mt = 0; mt < 2; mt++)
#pragma unroll
        for (int nt = 0; nt < 8; nt++)
#pragma unroll
            for (int i = 0; i < 4; i++) acc[mt][nt][i] = 0.f;

    for (int y = 0; y < 64; y++) {
        int buf = y & 1;
        if (y + 1 < 64) prefetchK((y + 1) * BN, buf ^ 1);
        if ((y & 1) == 0) prefetchVL(y >> 1, (y >> 1) & 1);
        cp_commit();

        // ---- S = Q K^T (tf32) ----
        float sc[4][4];
#pragma unroll
        for (int nt = 0; nt < 4; nt++)
#pragma unroll
            for (int i = 0; i < 4; i++) sc[nt][i] = 0.f;
        const float* ksB = (const float*)((char*)ks + buf * KSLOT);
#pragma unroll
        for (int kk = 0; kk < 4; kk++) {
            const float* br = ksB + (kk * 8 + lc) * KSTR + scol + lr;
#pragma unroll
            for (int nt = 0; nt < 4; nt++) {
                uint32 b0 = __float_as_uint(br[nt * 8]);
                uint32 b1 = __float_as_uint(br[4 * KSTR + nt * 8]);
                mma_tf32(sc[nt][0], sc[nt][1], sc[nt][2], sc[nt][3],
                         qa[kk][0], qa[kk][1], qa[kk][2], qa[kk][3], b0, b1);
            }
        }

        // ---- softmax (fp32 p), store PH, sum l ----
#pragma unroll
        for (int nt = 0; nt < 4; nt++) {
            float p0 = __expf(sc[nt][0]);
            float p1 = __expf(sc[nt][1]);
            float p2 = __expf(sc[nt][2]);
            float p3 = __expf(sc[nt][3]);
            lsum0 += p0 + p1;
            lsum1 += p2 + p3;
            int col = scol + nt * 8 + 2 * lc;
            *(float2*)&ph[(srow + lr) * PHSTR + col]     = make_float2(p0, p1);
            *(float2*)&ph[(srow + lr + 8) * PHSTR + col] = make_float2(p2, p3);
        }
        __syncthreads();   // PH complete

        // ---- fold PH row y into PL (vectorized gather + RMW) ----
        {
            int r0, r1; float w0, w1;
            if (y & 1) { int t = y >> 1; r0 = t; w0 = 0.75f;
                         r1 = (t + 1 < 32) ? t + 1 : 31; w1 = 0.25f; }
            else       { int t = y >> 1; r0 = (t - 1 >= 0) ? t - 1 : 0; w0 = 0.25f;
                         r1 = t; w1 = 0.75f; }
            bool merged = (r0 == r1);
            const float* Pn = ph + n_f * PHSTR + jg * 16;
            float4 v0 = *(const float4*)(Pn);
            float4 v1 = *(const float4*)(Pn + 4);
            float4 v2 = *(const float4*)(Pn + 8);
            float4 v3 = *(const float4*)(Pn + 12);
            float left  = (jg == 0) ? v0.x : Pn[-1];
            float right = (jg == 3) ? v3.w : Pn[16];
            float h[18] = {left, v0.x, v0.y, v0.z, v0.w,
                           v1.x, v1.y, v1.z, v1.w,
                           v2.x, v2.y, v2.z, v2.w,
                           v3.x, v3.y, v3.z, v3.w, right};
            float xs[8];
#pragma unroll
            for (int i = 0; i < 8; i++)
                xs[i] = 0.75f * (h[1 + 2 * i] + h[2 + 2 * i])
                      + 0.25f * (h[2 * i] + h[3 + 2 * i]);
            int idx = n_f * PLSTR + jg * 8;
            float* pl0 = plf + (r0 & 1) * (128 * PLSTR) + idx;
            if (merged) {
                float4 a = *(float4*)pl0, bb = *(float4*)(pl0 + 4);
                a.x += xs[0]; a.y += xs[1]; a.z += xs[2]; a.w += xs[3];
                bb.x += xs[4]; bb.y += xs[5]; bb.z += xs[6]; bb.w += xs[7];
                *(float4*)pl0 = a; *(float4*)(pl0 + 4) = bb;
            } else {
                float* pl1 = plf + (r1 & 1) * (128 * PLSTR) + idx;
                float4 a = *(float4*)pl0, bb = *(float4*)(pl0 + 4);
                a.x += w0 * xs[0]; a.y += w0 * xs[1];
                a.z += w0 * xs[2]; a.w += w0 * xs[3];
                bb.x += w0 * xs[4]; bb.y += w0 * xs[5];
                bb.z += w0 * xs[6]; bb.w += w0 * xs[7];
                *(float4*)pl0 = a; *(float4*)(pl0 + 4) = bb;
                float4 c = *(float4*)pl1, d = *(float4*)(pl1 + 4);
                c.x += w1 * xs[0]; c.y += w1 * xs[1];
                c.z += w1 * xs[2]; c.w += w1 * xs[3];
                d.x += w1 * xs[4]; d.y += w1 * xs[5];
                d.z += w1 * xs[6]; d.w += w1 * xs[7];
                *(float4*)pl1 = c; *(float4*)(pl1 + 4) = d;
            }
        }

        // ---- completion: PL -> bf16, zero, GEMM vs Vlow row ----
        bool complete = (((y & 1) == 0 && y >= 2) || y == 63);
        if (complete) {
            int rc = (y == 63) ? 31 : ((y - 2) >> 1);
            float* plc = plf + (rc & 1) * (128 * PLSTR) + n_f * PLSTR + jg * 8;
            float4 a = *(float4*)plc, bb = *(float4*)(plc + 4);
            __nv_bfloat162 o0 = __floats2bfloat162_rn(a.x, a.y);
            __nv_bfloat162 o1 = __floats2bfloat162_rn(a.z, a.w);
            __nv_bfloat162 o2 = __floats2bfloat162_rn(bb.x, bb.y);
            __nv_bfloat162 o3 = __floats2bfloat162_rn(bb.z, bb.w);
            *(uint4*)&plb[n_f * PLBSTR + jg * 8] = make_uint4(
                *(uint32*)&o0, *(uint32*)&o1, *(uint32*)&o2, *(uint32*)&o3);
            *(float4*)plc       = make_float4(0.f, 0.f, 0.f, 0.f);
            *(float4*)(plc + 4) = make_float4(0.f, 0.f, 0.f, 0.f);
            __syncthreads();   // PLb ready

            uint32 pB = sb + OFF_VL + (uint32)(rc & 1) * VLSLOT + pB_rel;
#pragma unroll
            for (int kk = 0; kk < 2; kk++) {
                uint32 a2[2][4];
#pragma unroll
                for (int mt = 0; mt < 2; mt++)
                    ldsm_x4(a2[mt][0], a2[mt][1], a2[mt][2], a2[mt][3],
                            pA_base + 2u * ((uint32)mt * 16 * PLBSTR
                                            + (uint32)kk * 16));
#pragma unroll
                for (int ntp = 0; ntp < 4; ntp++) {
                    uint32 b0, b1, b2, b3;
                    ldsm_x4(b0, b1, b2, b3,
                            pB + 2u * ((uint32)ntp * 16 * VLSTR
                                       + (uint32)kk * 16));
#pragma unroll
                    for (int mt = 0; mt < 2; mt++) {
                        mma_bf16(acc[mt][2 * ntp][0],     acc[mt][2 * ntp][1],
                                 acc[mt][2 * ntp][2],     acc[mt][2 * ntp][3],
                                 a2[mt][0], a2[mt][1], a2[mt][2], a2[mt][3],
                                 b0, b1);
                        mma_bf16(acc[mt][2 * ntp + 1][0], acc[mt][2 * ntp + 1][1],
                                 acc[mt][2 * ntp + 1][2], acc[mt][2 * ntp + 1][3],
                                 a2[mt][0], a2[mt][1], a2[mt][2], a2[mt][3],
                                 b2, b3);
                    }
                }
            }
        }
        cp_wait0();
        __syncthreads();   // K(y+1)/Vlow arrived; PH free; folds visible
    }

    // ---- half-row-sum reduction ----
    lsum0 += __shfl_xor_sync(0xffffffffu, lsum0, 1);
    lsum0 += __shfl_xor_sync(0xffffffffu, lsum0, 2);
    lsum1 += __shfl_xor_sync(0xffffffffu, lsum1, 1);
    lsum1 += __shfl_xor_sync(0xffffffffu, lsum1, 2);
    if (lc == 0) {
        lp[chalf * BM + srow + lr]     = lsum0;
        lp[chalf * BM + srow + lr + 8] = lsum1;
    }
    __syncthreads();

    // ---- epilogue: out = gamma * acc / l + query ----
    float gm = gamma[0];
    const float* qry = query + (size_t)b * CQi * NN + i0;
    float*       ob  = outp  + (size_t)b * CQi * NN + i0;
#pragma unroll
    for (int mt = 0; mt < 2; mt++) {
        int r0 = pvrow + mt * 16 + lr;
        int r1 = r0 + 8;
        float f0 = gm / (lp[r0] + lp[BM + r0]);
        float f1 = gm / (lp[r1] + lp[BM + r1]);
#pragma unroll
        for (int nt = 0; nt < 8; nt++) {
            int c = cb + nt * 8 + 2 * lc;
            size_t o00 = (size_t)c * NN + r0;
            size_t o01 = (size_t)(c + 1) * NN + r0;
            size_t o10 = (size_t)c * NN + r1;
            size_t o11 = (size_t)(c + 1) * NN + r1;
            ob[o00] = f0 * acc[mt][nt][0] + qry[o00];
            ob[o01] = f0 * acc[mt][nt][1] + qry[o01];
            ob[o10] = f1 * acc[mt][nt][2] + qry[o10];
            ob[o11] = f1 * acc[mt][nt][3] + qry[o11];
        }
    }
}

// ---------------- host launcher -------------------------------------------
extern "C" void kernel_launch(void* const* d_in, const int* in_sizes, int n_in,
                              void* d_out, int out_size)
{
    const float* query     = (const float*)d_in[0];
    const float* key_value = (const float*)d_in[1];
    const float* Wq = (const float*)d_in[2];
    const float* bq = (const float*)d_in[3];
    const float* Wk = (const float*)d_in[4];
    const float* bk = (const float*)d_in[5];
    const float* Wv = (const float*)d_in[6];
    const float* bv = (const float*)d_in[7];
    const float* gamma = (const float*)d_in[8];
    float* out = (float*)d_out;

    void* p;
    cudaGetSymbolAddress(&p, g_lo); float*         k_low = (float*)p;
    cudaGetSymbolAddress(&p, g_vl); __nv_bfloat16* v_low = (__nv_bfloat16*)p;
    cudaGetSymbolAddress(&p, g_q);  float*         qb    = (float*)p;
    cudaGetSymbolAddress(&p, g_k);  float*         kb    = (float*)p;

    size_t smQ = (2 * 32 * 260 + 2 * 32 * 36) * sizeof(float);
    size_t smV = (2 * 32 * 132 + 2 * 128 * 36) * sizeof(float);
    cudaFuncSetAttribute(proj_mma<256, 32, 256, 16, 64, 1>,
                         cudaFuncAttributeMaxDynamicSharedMemorySize, (int)smQ);
    cudaFuncSetAttribute(proj_mma<512, 32, 256, 16, 64, 0>,
                         cudaFuncAttributeMaxDynamicSharedMemorySize, (int)smQ);
    cudaFuncSetAttribute(proj_mma<512, 128, 128, 32, 64, 3>,
                         cudaFuncAttributeMaxDynamicSharedMemorySize, (int)smV);

    // 1) low-res projections (project-then-resize commutes)
    proj_mma<512, 32, 256, 16, 64, 0><<<dim3(NLOW / 256, BQ, 1), 256, smQ>>>(
        key_value, Wk, bk, k_low, 32, NLOW);
    proj_mma<512, 128, 128, 32, 64, 3><<<dim3(NLOW / 128, BQ, 2), 256, smV>>>(
        key_value, Wv, bv, v_low, 256, NLOW);
    // Q at full resolution
    proj_mma<256, 32, 256, 16, 64, 1><<<dim3(NN / 256, BQ, 1), 256, smQ>>>(
        query, Wq, bq, qb, 32, NN);

    // 2) upsample K only (V stays at low res; PV is folded in-kernel)
    upsample_kernel<0><<<(BQ * DQK * NN + 255) / 256, 256>>>(
        k_low, kb, BQ * DQK * NN);

    // 3) flash attention with folded PV + residual
    cudaFuncSetAttribute(attn_kernel, cudaFuncAttributeMaxDynamicSharedMemorySize,
                         ATT_SMEM);
    attn_kernel<<<dim3(NN / BM, BQ), 512, ATT_SMEM>>>(qb, kb, v_low, query,
                                                      gamma, out);
}

// round 17
// speedup vs baseline: 1.8284x; 1.0790x over previous
#include <cuda_runtime.h>
#include <cuda_bf16.h>
#include <cstdint>

// Problem constants
#define BQ   8
#define CQi  256
#define CKV  512
#define NN   4096
#define DQK  32
#define NLOW 1024    // 32x32 low-res spatial

typedef unsigned long long ull;
typedef unsigned int uint32;

// ---------------- scratch (static device globals; no allocations) ----------
__device__ float          g_lo[BQ * DQK * NLOW];   // lowres K (f32)
__device__ __nv_bfloat16  g_vl[BQ * CQi * NLOW];   // lowres V (bf16)
__device__ float          g_q [BQ * NN * DQK];     // Q^T [b][n][d] tf32
__device__ float          g_k [BQ * DQK * NN];     // K   [b][d][n] tf32

// ---------------- helpers ---------------------------------------------------
__device__ __forceinline__ float tf32r(float x) {
    uint32 u;
    asm("cvt.rna.tf32.f32 %0, %1;" : "=r"(u) : "f"(x));
    return __uint_as_float(u);
}
__device__ __forceinline__ void mma_tf32(
    float& c0, float& c1, float& c2, float& c3,
    uint32 a0, uint32 a1, uint32 a2, uint32 a3,
    uint32 b0, uint32 b1)
{
    asm volatile(
        "mma.sync.aligned.m16n8k8.row.col.f32.tf32.tf32.f32 "
        "{%0,%1,%2,%3}, {%4,%5,%6,%7}, {%8,%9}, {%0,%1,%2,%3};"
        : "+f"(c0), "+f"(c1), "+f"(c2), "+f"(c3)
        : "r"(a0), "r"(a1), "r"(a2), "r"(a3), "r"(b0), "r"(b1));
}
__device__ __forceinline__ void mma_bf16(
    float& c0, float& c1, float& c2, float& c3,
    uint32 a0, uint32 a1, uint32 a2, uint32 a3,
    uint32 b0, uint32 b1)
{
    asm volatile(
        "mma.sync.aligned.m16n8k16.row.col.f32.bf16.bf16.f32 "
        "{%0,%1,%2,%3}, {%4,%5,%6,%7}, {%8,%9}, {%0,%1,%2,%3};"
        : "+f"(c0), "+f"(c1), "+f"(c2), "+f"(c3)
        : "r"(a0), "r"(a1), "r"(a2), "r"(a3), "r"(b0), "r"(b1));
}
__device__ __forceinline__ void ldsm_x4(uint32& r0, uint32& r1, uint32& r2,
                                        uint32& r3, uint32 addr)
{
    asm volatile(
        "ldmatrix.sync.aligned.m8n8.x4.shared.b16 {%0,%1,%2,%3}, [%4];"
        : "=r"(r0), "=r"(r1), "=r"(r2), "=r"(r3) : "r"(addr));
}
__device__ __forceinline__ void cp16p(void* sdst, const void* gsrc) {
    uint32 s = (uint32)__cvta_generic_to_shared(sdst);
    asm volatile("cp.async.cg.shared.global [%0], [%1], 16;" :: "r"(s), "l"(gsrc));
}
__device__ __forceinline__ void cp_commit() {
    asm volatile("cp.async.commit_group;" ::: "memory");
}
__device__ __forceinline__ void cp_wait0() {
    asm volatile("cp.async.wait_group 0;" ::: "memory");
}

// ---------------- bilinear 2x upsample (half-pixel, clamped) ---------------
template <int OUTMODE>
__global__ void upsample_kernel(const float* __restrict__ src,
                                void* __restrict__ dst, int total)
{
    int idx = blockIdx.x * 256 + threadIdx.x;
    if (idx >= total) return;
    int x  = idx & 63;
    int y  = (idx >> 6) & 63;
    int cb = idx >> 12;
    float fx = 0.5f * (float)x - 0.25f;
    float fy = 0.5f * (float)y - 0.25f;
    float fx0 = floorf(fx), fy0 = floorf(fy);
    float wx = fx - fx0, wy = fy - fy0;
    int x0 = max((int)fx0, 0), x1 = min((int)fx0 + 1, 31);
    int y0 = max((int)fy0, 0), y1 = min((int)fy0 + 1, 31);
    const float* s = src + (size_t)cb * 1024;
    float v00 = s[y0 * 32 + x0], v01 = s[y0 * 32 + x1];
    float v10 = s[y1 * 32 + x0], v11 = s[y1 * 32 + x1];
    float top = v00 + wx * (v01 - v00);
    float bot = v10 + wx * (v11 - v10);
    float val = top + wy * (bot - top);
    if (OUTMODE == 0) ((float*)dst)[idx] = tf32r(val);
    else ((__nv_bfloat16*)dst)[idx] = __float2bfloat16(val);
}

// ---------------- tf32-mma 1x1 conv GEMM -----------------------------------
// OUTM: 0 = plain f32 [d][n], 1 = tf32 transposed [n][DQK], 3 = bf16 [d][n]
template <int CIN, int DT, int NT, int WM, int WN, int OUTM>
__global__ __launch_bounds__(256) void proj_mma(
    const float* __restrict__ in, const float* __restrict__ W,
    const float* __restrict__ bias, void* __restrict__ outp,
    int dout_total, int nspat)
{
    constexpr int BK  = 32;
    constexpr int NTP = NT + 4;
    constexpr int WSP = 36;
    constexpr int KCH = CIN / BK;
    constexpr int MT  = WM / 16;
    constexpr int NTl = WN / 8;
    constexpr int WARPS_N = NT / WN;

    extern __shared__ float smx[];
    float* ins = smx;
    float* Ws  = smx + 2 * BK * NTP;

    int tid  = threadIdx.x;
    int warp = tid >> 5, lane = tid & 31;
    int lr = lane >> 2, lc = lane & 3;
    int nwarp = warp % WARPS_N, mwarp = warp / WARPS_N;
    int mb = mwarp * WM, nb = nwarp * WN;

    int b  = blockIdx.y;
    int n0 = blockIdx.x * NT;
    int d0 = blockIdx.z * DT;

    const float* inb = in + (size_t)b * CIN * nspat + n0;

    float acc[MT][NTl][4];
#pragma unroll
    for (int mt = 0; mt < MT; mt++)
#pragma unroll
        for (int nt = 0; nt < NTl; nt++)
#pragma unroll
            for (int i = 0; i < 4; i++) acc[mt][nt][i] = 0.f;

    auto prefetch = [&](int kc, int pb) {
        float* insB = ins + pb * BK * NTP;
        float* WsB  = Ws  + pb * DT * WSP;
        constexpr int INIT = BK * NT / 4 / 256;
#pragma unroll
        for (int it = 0; it < INIT; it++) {
            int idx = tid + it * 256;
            int c = idx / (NT / 4), j4 = (idx % (NT / 4)) * 4;
            cp16p(insB + c * NTP + j4, inb + (size_t)(kc * BK + c) * nspat + j4);
        }
        constexpr int WIT = DT * 8 / 256;
#pragma unroll
        for (int it = 0; it < (WIT > 0 ? WIT : 1); it++) {
            int idx = tid + it * 256;
            if (idx < DT * 8) {
                int d = idx >> 3, cj = (idx & 7) * 4;
                cp16p(WsB + d * WSP + cj, W + (size_t)(d0 + d) * CIN + kc * BK + cj);
            }
        }
    };

    prefetch(0, 0);
    cp_commit();
    cp_wait0();
    __syncthreads();

    for (int kc = 0; kc < KCH; kc++) {
        int buf = kc & 1;
        if (kc + 1 < KCH) { prefetch(kc + 1, buf ^ 1); cp_commit(); }
        const float* insB = ins + buf * BK * NTP;
        const float* WsB  = Ws  + buf * DT * WSP;
#pragma unroll
        for (int kk = 0; kk < 4; kk++) {
            uint32 a[MT][4];
#pragma unroll
            for (int mt = 0; mt < MT; mt++) {
                const float* ar = WsB + (mb + mt * 16 + lr) * WSP + kk * 8 + lc;
                a[mt][0] = __float_as_uint(ar[0]);
                a[mt][1] = __float_as_uint(ar[8 * WSP]);
                a[mt][2] = __float_as_uint(ar[4]);
                a[mt][3] = __float_as_uint(ar[8 * WSP + 4]);
            }
            const float* br = insB + (kk * 8 + lc) * NTP + nb + lr;
#pragma unroll
            for (int nt = 0; nt < NTl; nt++) {
                uint32 b0 = __float_as_uint(br[nt * 8]);
                uint32 b1 = __float_as_uint(br[4 * NTP + nt * 8]);
#pragma unroll
                for (int mt = 0; mt < MT; mt++)
                    mma_tf32(acc[mt][nt][0], acc[mt][nt][1],
                             acc[mt][nt][2], acc[mt][nt][3],
                             a[mt][0], a[mt][1], a[mt][2], a[mt][3], b0, b1);
            }
        }
        cp_wait0();
        __syncthreads();
    }

#pragma unroll
    for (int mt = 0; mt < MT; mt++) {
        int dA = d0 + mb + mt * 16 + lr;
        float bA = bias[dA], bB = bias[dA + 8];
        if (OUTM == 1) {
            float* op = (float*)outp;
#pragma unroll
            for (int nt = 0; nt < NTl; nt++) {
                int nc = n0 + nb + nt * 8 + 2 * lc;
                float* o = op + ((size_t)b * nspat + nc) * DQK;
                o[dA]           = tf32r(acc[mt][nt][0] + bA);
                o[DQK + dA]     = tf32r(acc[mt][nt][1] + bA);
                o[dA + 8]       = tf32r(acc[mt][nt][2] + bB);
                o[DQK + dA + 8] = tf32r(acc[mt][nt][3] + bB);
            }
        } else if (OUTM == 0) {
            float* oA = (float*)outp + ((size_t)b * dout_total + dA) * nspat + n0 + nb;
            float* oB = oA + (size_t)8 * nspat;
#pragma unroll
            for (int nt = 0; nt < NTl; nt++) {
                int col = nt * 8 + 2 * lc;
                *(float2*)&oA[col] = make_float2(acc[mt][nt][0] + bA,
                                                acc[mt][nt][1] + bA);
                *(float2*)&oB[col] = make_float2(acc[mt][nt][2] + bB,
                                                acc[mt][nt][3] + bB);
            }
        } else {
            __nv_bfloat16* oA = (__nv_bfloat16*)outp
                + ((size_t)b * dout_total + dA) * nspat + n0 + nb;
            __nv_bfloat16* oB = oA + (size_t)8 * nspat;
#pragma unroll
            for (int nt = 0; nt < NTl; nt++) {
                int col = nt * 8 + 2 * lc;
                *(__nv_bfloat162*)&oA[col] =
                    __floats2bfloat162_rn(acc[mt][nt][0] + bA, acc[mt][nt][1] + bA);
                *(__nv_bfloat162*)&oB[col] =
                    __floats2bfloat162_rn(acc[mt][nt][2] + bB, acc[mt][nt][3] + bB);
            }
        }
    }
}

// ---------------- flash attention with folded low-res PV -------------------
// Identical to R16 except PH is double-buffered -> ONE barrier per iteration
// (the end-of-loop barrier is removed; safety argument in commit message).
#define BM 128
#define BN 64
#define QSTR 36     // f32
#define KSTR 72     // f32
#define PHSTR 68    // f32 (64 + 4 pad)
#define PLSTR 36    // f32 (32 + 4 pad, 16B-aligned rows)
#define PLBSTR 40   // bf16 (32 + 8 pad)
#define VLSTR 40    // bf16

#define KSLOT  9216                 // 32*72*4
#define PHSLOT (128 * PHSTR * 4)    // 34816
#define PLSLOT (128 * PLSTR * 4)    // 18432
#define VLSLOT (256 * VLSTR * 2)    // 20480

#define OFF_QS  0                   // 18432
#define OFF_K   18432               // 18432  -> 36864
#define OFF_PH  36864               // 2*34816-> 106496
#define OFF_PL  106496              // 36864  -> 143360
#define OFF_PLB 143360              // 10240  -> 153600
#define OFF_VL  153600              // 40960  -> 194560
#define OFF_L   194560              // 1024   -> 195584
#define ATT_SMEM 195584

__global__ __launch_bounds__(512, 1) void attn_kernel(
    const float* __restrict__ qT, const float* __restrict__ k,
    const __nv_bfloat16* __restrict__ vl, const float* __restrict__ query,
    const float* __restrict__ gamma, float* __restrict__ outp)
{
    extern __shared__ char smem[];
    uint32 sb = (uint32)__cvta_generic_to_shared(smem);
    float*         qs  = (float*)(smem + OFF_QS);
    float*         ks  = (float*)(smem + OFF_K);
    float*         ph  = (float*)(smem + OFF_PH);
    float*         plf = (float*)(smem + OFF_PL);
    __nv_bfloat16* plb = (__nv_bfloat16*)(smem + OFF_PLB);
    __nv_bfloat16* vls = (__nv_bfloat16*)(smem + OFF_VL);
    float*         lp  = (float*)(smem + OFF_L);

    int tid  = threadIdx.x;
    int warp = tid >> 5;
    int lane = tid & 31;
    int lr = lane >> 2, lc = lane & 3;
    int b  = blockIdx.y;
    int i0 = blockIdx.x * BM;

    int srow  = (warp & 7) * 16;
    int chalf = warp >> 3;
    int scol  = chalf * 32;
    int pvrow = (warp & 3) * 32;
    int cb    = (warp >> 2) * 64;

    int n_f = tid >> 2;
    int jg  = tid & 3;

    const float*         qTb = qT + ((size_t)b * NN + i0) * DQK;
    const float*         kb  = k  + (size_t)b * DQK * NN;
    const __nv_bfloat16* vlb = vl + (size_t)b * CQi * NLOW;

    auto prefetchK = [&](int m0, int pb) {
        int d = tid >> 4, ch = tid & 15;
        cp16p((char*)ks + pb * KSLOT + d * (KSTR * 4) + ch * 16,
              kb + (size_t)d * NN + m0 + ch * 4);
    };
    auto prefetchVL = [&](int r, int slot) {
#pragma unroll
        for (int it = 0; it < 2; it++) {
            int idx = tid + it * 512;
            int c = idx >> 2, ch = idx & 3;
            cp16p((char*)vls + slot * VLSLOT + c * (VLSTR * 2) + ch * 16,
                  vlb + (size_t)c * NLOW + r * 32 + ch * 8);
        }
    };

    // ---- prolog: zero PL, load Q + K(0) ----
    for (int i = tid; i < 2 * 128 * PLSTR; i += 512) plf[i] = 0.f;
#pragma unroll
    for (int it = 0; it < 2; it++) {
        int idx = tid + it * 512;
        int i = idx >> 3, ch = idx & 7;
        cp16p((char*)qs + i * (QSTR * 4) + ch * 16, qTb + i * DQK + ch * 4);
    }
    prefetchK(0, 0);
    cp_commit();
    cp_wait0();
    __syncthreads();

    // ---- hoist Q fragments ----
    uint32 qa[4][4];
#pragma unroll
    for (int kk = 0; kk < 4; kk++) {
        const float* ar = qs + (srow + lr) * QSTR + kk * 8 + lc;
        qa[kk][0] = __float_as_uint(ar[0]);
        qa[kk][1] = __float_as_uint(ar[8 * QSTR]);
        qa[kk][2] = __float_as_uint(ar[4]);
        qa[kk][3] = __float_as_uint(ar[8 * QSTR + 4]);
    }

    uint32 pA_base = sb + OFF_PLB
        + 2u * ((uint32)(pvrow + (lane & 15)) * PLBSTR + ((lane >> 1) & 8));
    uint32 pB_rel = 2u * ((uint32)(cb + (lane & 7) + ((lane >> 1) & 8)) * VLSTR
                          + (lane & 8));

    float lsum0 = 0.f, lsum1 = 0.f;
    float acc[2][8][4];
#pragma unroll
    for (int mt = 0; mt < 2; mt++)
#pragma unroll
        for (int nt = 0; nt < 8; nt++)
#pragma unroll
            for (int i = 0; i < 4; i++) acc[mt][nt][i] = 0.f;

    for (int y = 0; y < 64; y++) {
        int buf = y & 1;
        if (y + 1 < 64) prefetchK((y + 1) * BN, buf ^ 1);
        if ((y & 1) == 0) prefetchVL(y >> 1, (y >> 1) & 1);
        cp_commit();

        // ---- S = Q K^T (tf32) ----
        float sc[4][4];
#pragma unroll
        for (int nt = 0; nt < 4; nt++)
#pragma unroll
            for (int i = 0; i < 4; i++) sc[nt][i] = 0.f;
        const float* ksB = (const float*)((char*)ks + buf * KSLOT);
#pragma unroll
        for (int kk = 0; kk < 4; kk++) {
            const float* br = ksB + (kk * 8 + lc) * KSTR + scol + lr;
#pragma unroll
            for (int nt = 0; nt < 4; nt++) {
                uint32 b0 = __float_as_uint(br[nt * 8]);
                uint32 b1 = __float_as_uint(br[4 * KSTR + nt * 8]);
                mma_tf32(sc[nt][0], sc[nt][1], sc[nt][2], sc[nt][3],
                         qa[kk][0], qa[kk][1], qa[kk][2], qa[kk][3], b0, b1);
            }
        }

        // ---- softmax (fp32 p), store PH[buf], sum l ----
        float* phW = ph + buf * (128 * PHSTR);
#pragma unroll
        for (int nt = 0; nt < 4; nt++) {
            float p0 = __expf(sc[nt][0]);
            float p1 = __expf(sc[nt][1]);
            float p2 = __expf(sc[nt][2]);
            float p3 = __expf(sc[nt][3]);
            lsum0 += p0 + p1;
            lsum1 += p2 + p3;
            int col = scol + nt * 8 + 2 * lc;
            *(float2*)&phW[(srow + lr) * PHSTR + col]     = make_float2(p0, p1);
            *(float2*)&phW[(srow + lr + 8) * PHSTR + col] = make_float2(p2, p3);
        }
        cp_wait0();
        __syncthreads();   // SINGLE barrier: PH(y) + K(y+1)/VL visible

        // ---- fold PH[buf] row y into PL (vectorized gather + RMW) ----
        {
            int r0, r1; float w0, w1;
            if (y & 1) { int t = y >> 1; r0 = t; w0 = 0.75f;
                         r1 = (t + 1 < 32) ? t + 1 : 31; w1 = 0.25f; }
            else       { int t = y >> 1; r0 = (t - 1 >= 0) ? t - 1 : 0; w0 = 0.25f;
                         r1 = t; w1 = 0.75f; }
            bool merged = (r0 == r1);
            const float* Pn = phW + n_f * PHSTR + jg * 16;
            float4 v0 = *(const float4*)(Pn);
            float4 v1 = *(const float4*)(Pn + 4);
            float4 v2 = *(const float4*)(Pn + 8);
            float4 v3 = *(const float4*)(Pn + 12);
            float left  = (jg == 0) ? v0.x : Pn[-1];
            float right = (jg == 3) ? v3.w : Pn[16];
            float h[18] = {left, v0.x, v0.y, v0.z, v0.w,
                           v1.x, v1.y, v1.z, v1.w,
                           v2.x, v2.y, v2.z, v2.w,
                           v3.x, v3.y, v3.z, v3.w, right};
            float xs[8];
#pragma unroll
            for (int i = 0; i < 8; i++)
                xs[i] = 0.75f * (h[1 + 2 * i] + h[2 + 2 * i])
                      + 0.25f * (h[2 * i] + h[3 + 2 * i]);
            int idx = n_f * PLSTR + jg * 8;
            float* pl0 = plf + (r0 & 1) * (128 * PLSTR) + idx;
            if (merged) {
                float4 a = *(float4*)pl0, bb = *(float4*)(pl0 + 4);
                a.x += xs[0]; a.y += xs[1]; a.z += xs[2]; a.w += xs[3];
                bb.x += xs[4]; bb.y += xs[5]; bb.z += xs[6]; bb.w += xs[7];
                *(float4*)pl0 = a; *(float4*)(pl0 + 4) = bb;
            } else {
                float* pl1 = plf + (r1 & 1) * (128 * PLSTR) + idx;
                float4 a = *(float4*)pl0, bb = *(float4*)(pl0 + 4);
                a.x += w0 * xs[0]; a.y += w0 * xs[1];
                a.z += w0 * xs[2]; a.w += w0 * xs[3];
                bb.x += w0 * xs[4]; bb.y += w0 * xs[5];
                bb.z += w0 * xs[6]; bb.w += w0 * xs[7];
                *(float4*)pl0 = a; *(float4*)(pl0 + 4) = bb;
                float4 c = *(float4*)pl1, d = *(float4*)(pl1 + 4);
                c.x += w1 * xs[0]; c.y += w1 * xs[1];
                c.z += w1 * xs[2]; c.w += w1 * xs[3];
                d.x += w1 * xs[4]; d.y += w1 * xs[5];
                d.z += w1 * xs[6]; d.w += w1 * xs[7];
                *(float4*)pl1 = c; *(float4*)(pl1 + 4) = d;
            }
        }

        // ---- completion: PL -> bf16, zero, GEMM vs Vlow row ----
        bool complete = (((y & 1) == 0 && y >= 2) || y == 63);
        if (complete) {
            int rc = (y == 63) ? 31 : ((y - 2) >> 1);
            float* plc = plf + (rc & 1) * (128 * PLSTR) + n_f * PLSTR + jg * 8;
            float4 a = *(float4*)plc, bb = *(float4*)(plc + 4);
            __nv_bfloat162 o0 = __floats2bfloat162_rn(a.x, a.y);
            __nv_bfloat162 o1 = __floats2bfloat162_rn(a.z, a.w);
            __nv_bfloat162 o2 = __floats2bfloat162_rn(bb.x, bb.y);
            __nv_bfloat162 o3 = __floats2bfloat162_rn(bb.z, bb.w);
            *(uint4*)&plb[n_f * PLBSTR + jg * 8] = make_uint4(
                *(uint32*)&o0, *(uint32*)&o1, *(uint32*)&o2, *(uint32*)&o3);
            *(float4*)plc       = make_float4(0.f, 0.f, 0.f, 0.f);
            *(float4*)(plc + 4) = make_float4(0.f, 0.f, 0.f, 0.f);
            __syncthreads();   // PLb visible for cross-thread ldmatrix

            uint32 pB = sb + OFF_VL + (uint32)(rc & 1) * VLSLOT + pB_rel;
#pragma unroll
            for (int kk = 0; kk < 2; kk++) {
                uint32 a2[2][4];
#pragma unroll
                for (int mt = 0; mt < 2; mt++)
                    ldsm_x4(a2[mt][0], a2[mt][1], a2[mt][2], a2[mt][3],
                            pA_base + 2u * ((uint32)mt * 16 * PLBSTR
                                            + (uint32)kk * 16));
#pragma unroll
                for (int ntp = 0; ntp < 4; ntp++) {
                    uint32 b0, b1, b2, b3;
                    ldsm_x4(b0, b1, b2, b3,
                            pB + 2u * ((uint32)ntp * 16 * VLSTR
                                       + (uint32)kk * 16));
#pragma unroll
                    for (int mt = 0; mt < 2; mt++) {
                        mma_bf16(acc[mt][2 * ntp][0],     acc[mt][2 * ntp][1],
                                 acc[mt][2 * ntp][2],     acc[mt][2 * ntp][3],
                                 a2[mt][0], a2[mt][1], a2[mt][2], a2[mt][3],
                                 b0, b1);
                        mma_bf16(acc[mt][2 * ntp + 1][0], acc[mt][2 * ntp + 1][1],
                                 acc[mt][2 * ntp + 1][2], acc[mt][2 * ntp + 1][3],
                                 a2[mt][0], a2[mt][1], a2[mt][2], a2[mt][3],
                                 b2, b3);
                    }
                }
            }
        }
        // no end-of-loop barrier: PH is double-buffered, PL/PLb thread- or
        // barrier-protected, K/VL slots have >=1 barrier before overwrite.
    }

    __syncthreads();   // all folds/GEMMs done before reductions

    // ---- half-row-sum reduction ----
    lsum0 += __shfl_xor_sync(0xffffffffu, lsum0, 1);
    lsum0 += __shfl_xor_sync(0xffffffffu, lsum0, 2);
    lsum1 += __shfl_xor_sync(0xffffffffu, lsum1, 1);
    lsum1 += __shfl_xor_sync(0xffffffffu, lsum1, 2);
    if (lc == 0) {
        lp[chalf * BM + srow + lr]     = lsum0;
        lp[chalf * BM + srow + lr + 8] = lsum1;
    }
    __syncthreads();

    // ---- epilogue: out = gamma * acc / l + query ----
    float gm = gamma[0];
    const float* qry = query + (size_t)b * CQi * NN + i0;
    float*       ob  = outp  + (size_t)b * CQi * NN + i0;
#pragma unroll
    for (int mt = 0; mt < 2; mt++) {
        int r0 = pvrow + mt * 16 + lr;
        int r1 = r0 + 8;
        float f0 = gm / (lp[r0] + lp[BM + r0]);
        float f1 = gm / (lp[r1] + lp[BM + r1]);
#pragma unroll
        for (int nt = 0; nt < 8; nt++) {
            int c = cb + nt * 8 + 2 * lc;
            size_t o00 = (size_t)c * NN + r0;
            size_t o01 = (size_t)(c + 1) * NN + r0;
            size_t o10 = (size_t)c * NN + r1;
            size_t o11 = (size_t)(c + 1) * NN + r1;
            ob[o00] = f0 * acc[mt][nt][0] + qry[o00];
            ob[o01] = f0 * acc[mt][nt][1] + qry[o01];
            ob[o10] = f1 * acc[mt][nt][2] + qry[o10];
            ob[o11] = f1 * acc[mt][nt][3] + qry[o11];
        }
    }
}

// ---------------- host launcher -------------------------------------------
extern "C" void kernel_launch(void* const* d_in, const int* in_sizes, int n_in,
                              void* d_out, int out_size)
{
    const float* query     = (const float*)d_in[0];
    const float* key_value = (const float*)d_in[1];
    const float* Wq = (const float*)d_in[2];
    const float* bq = (const float*)d_in[3];
    const float* Wk = (const float*)d_in[4];
    const float* bk = (const float*)d_in[5];
    const float* Wv = (const float*)d_in[6];
    const float* bv = (const float*)d_in[7];
    const float* gamma = (const float*)d_in[8];
    float* out = (float*)d_out;

    void* p;
    cudaGetSymbolAddress(&p, g_lo); float*         k_low = (float*)p;
    cudaGetSymbolAddress(&p, g_vl); __nv_bfloat16* v_low = (__nv_bfloat16*)p;
    cudaGetSymbolAddress(&p, g_q);  float*         qb    = (float*)p;
    cudaGetSymbolAddress(&p, g_k);  float*         kb    = (float*)p;

    size_t smQ = (2 * 32 * 260 + 2 * 32 * 36) * sizeof(float);
    size_t smV = (2 * 32 * 132 + 2 * 128 * 36) * sizeof(float);
    cudaFuncSetAttribute(proj_mma<256, 32, 256, 16, 64, 1>,
                         cudaFuncAttributeMaxDynamicSharedMemorySize, (int)smQ);
    cudaFuncSetAttribute(proj_mma<512, 32, 256, 16, 64, 0>,
                         cudaFuncAttributeMaxDynamicSharedMemorySize, (int)smQ);
    cudaFuncSetAttribute(proj_mma<512, 128, 128, 32, 64, 3>,
                         cudaFuncAttributeMaxDynamicSharedMemorySize, (int)smV);

    // 1) low-res projections (project-then-resize commutes)
    proj_mma<512, 32, 256, 16, 64, 0><<<dim3(NLOW / 256, BQ, 1), 256, smQ>>>(
        key_value, Wk, bk, k_low, 32, NLOW);
    proj_mma<512, 128, 128, 32, 64, 3><<<dim3(NLOW / 128, BQ, 2), 256, smV>>>(
        key_value, Wv, bv, v_low, 256, NLOW);
    // Q at full resolution
    proj_mma<256, 32, 256, 16, 64, 1><<<dim3(NN / 256, BQ, 1), 256, smQ>>>(
        query, Wq, bq, qb, 32, NN);

    // 2) upsample K only (V stays at low res; PV is folded in-kernel)
    upsample_kernel<0><<<(BQ * DQK * NN + 255) / 256, 256>>>(
        k_low, kb, BQ * DQK * NN);

    // 3) flash attention with folded PV + residual
    cudaFuncSetAttribute(attn_kernel, cudaFuncAttributeMaxDynamicSharedMemorySize,
                         ATT_SMEM);
    attn_kernel<<<dim3(NN / BM, BQ), 512, ATT_SMEM>>>(qb, kb, v_low, query,
                                                      gamma, out);
}